// round 10
// baseline (speedup 1.0000x reference)
#include <cuda_runtime.h>
#include <math.h>

#define DIMV 512
#define HIDV 2048
#define NBATCH 4
#define SLV 4096
#define TOK (NBATCH*SLV)          // 16384
#define SA 132                    // smem row stride (128 + 4 pad), 132*4B % 16 == 0

// ---------------- scratch (device globals: no allocation allowed) ----------------
__device__ float g_Wk[DIMV*DIMV];
__device__ float g_Wv[DIMV*DIMV];
__device__ float g_Wo[DIMV*DIMV];
__device__ float g_W1[HIDV*DIMV];
__device__ float g_W2[DIMV*HIDV];
__device__ float g_xk[TOK*DIMV];
__device__ float g_xv[TOK*DIMV];
__device__ float g_h[TOK*DIMV];
__device__ float g_hres[TOK*DIMV];
__device__ float g_ff1[TOK*HIDV];                 // 33.5M floats
__device__ float g_scores[NBATCH*SLV*SLV];        // 67.1M floats (268 MB)
__device__ unsigned char g_flags[32*32];          // 1 = tile fully masked (<= -1e8)

// ---------------- f32x2 helpers (Blackwell packed fp32 FMA) ----------------
__device__ __forceinline__ void ffma2(unsigned long long &d, unsigned long long a, unsigned long long b){
    asm("fma.rn.f32x2 %0, %1, %2, %0;" : "+l"(d) : "l"(a), "l"(b));
}
__device__ __forceinline__ unsigned long long pk2(float x){
    unsigned long long r; asm("mov.b64 %0, {%1, %1};" : "=l"(r) : "f"(x)); return r;
}
union F2U { unsigned long long u; float2 f; };

// transpose-store a float4 (4 consecutive k) of one row into As[k][m]
__device__ __forceinline__ void sts4t(float* s, int k, int m, float4 v){
    s[(k+0)*SA+m]=v.x; s[(k+1)*SA+m]=v.y; s[(k+2)*SA+m]=v.z; s[(k+3)*SA+m]=v.w;
}

// 16-step inner product on one smem tile pair; acc pairs along n (low lane = even col)
__device__ __forceinline__ void mm16(const float* __restrict__ As, const float* __restrict__ Bs,
                                     int m0, int n0, unsigned long long (&acc)[8][4]){
    #pragma unroll
    for (int kk=0; kk<16; kk++){
        const float* ar = As + kk*SA + m0;
        float4 a0 = *(const float4*)(ar);
        float4 a1 = *(const float4*)(ar+4);
        const float* br = Bs + kk*SA + n0;
        ulonglong2 q0 = *(const ulonglong2*)(br);
        ulonglong2 q1 = *(const ulonglong2*)(br+4);
        unsigned long long b0=q0.x, b1=q0.y, b2=q1.x, b3=q1.y;
        unsigned long long a;
        a=pk2(a0.x); ffma2(acc[0][0],a,b0); ffma2(acc[0][1],a,b1); ffma2(acc[0][2],a,b2); ffma2(acc[0][3],a,b3);
        a=pk2(a0.y); ffma2(acc[1][0],a,b0); ffma2(acc[1][1],a,b1); ffma2(acc[1][2],a,b2); ffma2(acc[1][3],a,b3);
        a=pk2(a0.z); ffma2(acc[2][0],a,b0); ffma2(acc[2][1],a,b1); ffma2(acc[2][2],a,b2); ffma2(acc[2][3],a,b3);
        a=pk2(a0.w); ffma2(acc[3][0],a,b0); ffma2(acc[3][1],a,b1); ffma2(acc[3][2],a,b2); ffma2(acc[3][3],a,b3);
        a=pk2(a1.x); ffma2(acc[4][0],a,b0); ffma2(acc[4][1],a,b1); ffma2(acc[4][2],a,b2); ffma2(acc[4][3],a,b3);
        a=pk2(a1.y); ffma2(acc[5][0],a,b0); ffma2(acc[5][1],a,b1); ffma2(acc[5][2],a,b2); ffma2(acc[5][3],a,b3);
        a=pk2(a1.z); ffma2(acc[6][0],a,b0); ffma2(acc[6][1],a,b1); ffma2(acc[6][2],a,b2); ffma2(acc[6][3],a,b3);
        a=pk2(a1.w); ffma2(acc[7][0],a,b0); ffma2(acc[7][1],a,b1); ffma2(acc[7][2],a,b2); ffma2(acc[7][3],a,b3);
    }
}

// ---------------- weight materialization: W = mu + exp(ls)*eps ----------------
__global__ void make_w_kernel(const float* __restrict__ mu, const float* __restrict__ ls,
                              const float* __restrict__ eps, float* __restrict__ w, int n){
    int i = blockIdx.x*256 + threadIdx.x;
    if (i < n) w[i] = fmaf(expf(ls[i]), eps[i], mu[i]);
}

// ---------------- flags: 1 if whole 128x128 mask tile <= -1e8 ----------------
__global__ void flags_kernel(const float* __restrict__ mask){
    int qb=blockIdx.y, kb=blockIdx.x, tid=threadIdx.x;
    int any = 0;
    #pragma unroll 4
    for (int i=0;i<64;i++){
        int idx=i*256+tid; int r=idx>>7, c=idx&127;
        float v = mask[(size_t)(qb*128+r)*SLV + kb*128+c];
        any |= (v > -1e8f) ? 1 : 0;
    }
    int a = __syncthreads_or(any);
    if (tid==0) g_flags[qb*32+kb] = (a==0) ? 1 : 0;
}

// ---------------- generic NT GEMM: C[M,N] = A[M,K] * B[N,K]^T (+epilogue) ----------------
// epi: 0 = none, 1 = C += aux (same layout), 2 = relu
__global__ void __launch_bounds__(256,2)
gemm_nt_kernel(const float* __restrict__ A, const float* __restrict__ B,
               float* __restrict__ C, const float* __restrict__ aux,
               int M, int N, int K, int epi)
{
    (void)M;
    __shared__ __align__(16) float As[2][16*SA];
    __shared__ __align__(16) float Bs[2][16*SA];
    const int tid = threadIdx.x;
    const int bm = blockIdx.y*128;
    const int bn = blockIdx.x*128;

    const int c0=tid, c1=tid+256;
    const int r0=c0>>2, k0=(c0&3)*4;
    const int r1=c1>>2, k1=(c1&3)*4;
    const float* pa0 = A + (size_t)(bm+r0)*K + k0;
    const float* pa1 = A + (size_t)(bm+r1)*K + k1;
    const float* pb0 = B + (size_t)(bn+r0)*K + k0;
    const float* pb1 = B + (size_t)(bn+r1)*K + k1;

    const int tx=tid&15, ty=tid>>4;
    const int m0=ty*8, n0=tx*8;

    unsigned long long acc[8][4];
    #pragma unroll
    for (int i=0;i<8;i++){
        #pragma unroll
        for (int j=0;j<4;j++) acc[i][j]=0ull;
    }

    const int nt = K>>4;
    float4 ra0 = *(const float4*)pa0;
    float4 ra1 = *(const float4*)pa1;
    float4 rb0 = *(const float4*)pb0;
    float4 rb1 = *(const float4*)pb1;
    sts4t(As[0],k0,r0,ra0); sts4t(As[0],k1,r1,ra1);
    sts4t(Bs[0],k0,r0,rb0); sts4t(Bs[0],k1,r1,rb1);
    __syncthreads();

    for (int t=0; t<nt; t++){
        if (t+1 < nt){
            int ko=(t+1)*16;
            ra0 = *(const float4*)(pa0+ko);
            ra1 = *(const float4*)(pa1+ko);
            rb0 = *(const float4*)(pb0+ko);
            rb1 = *(const float4*)(pb1+ko);
        }
        mm16(As[t&1], Bs[t&1], m0, n0, acc);
        if (t+1 < nt){
            float* a2=As[(t+1)&1]; float* b2=Bs[(t+1)&1];
            sts4t(a2,k0,r0,ra0); sts4t(a2,k1,r1,ra1);
            sts4t(b2,k0,r0,rb0); sts4t(b2,k1,r1,rb1);
            __syncthreads();
        }
    }

    #pragma unroll
    for (int i=0;i<8;i++){
        size_t off = (size_t)(bm+m0+i)*N + bn + n0;
        F2U u0,u1,u2,u3;
        u0.u=acc[i][0]; u1.u=acc[i][1]; u2.u=acc[i][2]; u3.u=acc[i][3];
        float4 o0 = make_float4(u0.f.x,u0.f.y,u1.f.x,u1.f.y);
        float4 o1 = make_float4(u2.f.x,u2.f.y,u3.f.x,u3.f.y);
        if (epi==1){
            float4 x0 = *(const float4*)(aux+off);
            float4 x1 = *(const float4*)(aux+off+4);
            o0.x+=x0.x; o0.y+=x0.y; o0.z+=x0.z; o0.w+=x0.w;
            o1.x+=x1.x; o1.y+=x1.y; o1.z+=x1.z; o1.w+=x1.w;
        } else if (epi==2){
            o0.x=fmaxf(o0.x,0.f); o0.y=fmaxf(o0.y,0.f); o0.z=fmaxf(o0.z,0.f); o0.w=fmaxf(o0.w,0.f);
            o1.x=fmaxf(o1.x,0.f); o1.y=fmaxf(o1.y,0.f); o1.z=fmaxf(o1.z,0.f); o1.w=fmaxf(o1.w,0.f);
        }
        *(float4*)(C+off)=o0; *(float4*)(C+off+4)=o1;
    }
}

// ---------------- scores: S[b] = (x[b] @ xk[b]^T)/sqrt(D) + mask, skip fully-masked tiles --------
__global__ void __launch_bounds__(256,2)
scores_kernel(const float* __restrict__ x, const float* __restrict__ mask)
{
    const int b = blockIdx.z, qb=blockIdx.y, kb=blockIdx.x;
    if (g_flags[qb*32+kb]) return;
    const float* A = x   + (size_t)b*SLV*DIMV;
    const float* B = g_xk + (size_t)b*SLV*DIMV;

    __shared__ __align__(16) float As[2][16*SA];
    __shared__ __align__(16) float Bs[2][16*SA];
    const int tid = threadIdx.x;
    const int bm = qb*128, bn = kb*128;

    const int c0=tid, c1=tid+256;
    const int r0=c0>>2, k0=(c0&3)*4;
    const int r1=c1>>2, k1=(c1&3)*4;
    const float* pa0 = A + (size_t)(bm+r0)*DIMV + k0;
    const float* pa1 = A + (size_t)(bm+r1)*DIMV + k1;
    const float* pb0 = B + (size_t)(bn+r0)*DIMV + k0;
    const float* pb1 = B + (size_t)(bn+r1)*DIMV + k1;

    const int tx=tid&15, ty=tid>>4;
    const int m0=ty*8, n0=tx*8;

    unsigned long long acc[8][4];
    #pragma unroll
    for (int i=0;i<8;i++){
        #pragma unroll
        for (int j=0;j<4;j++) acc[i][j]=0ull;
    }

    const int nt = DIMV>>4;   // 32
    float4 ra0 = *(const float4*)pa0;
    float4 ra1 = *(const float4*)pa1;
    float4 rb0 = *(const float4*)pb0;
    float4 rb1 = *(const float4*)pb1;
    sts4t(As[0],k0,r0,ra0); sts4t(As[0],k1,r1,ra1);
    sts4t(Bs[0],k0,r0,rb0); sts4t(Bs[0],k1,r1,rb1);
    __syncthreads();

    for (int t=0; t<nt; t++){
        if (t+1 < nt){
            int ko=(t+1)*16;
            ra0 = *(const float4*)(pa0+ko);
            ra1 = *(const float4*)(pa1+ko);
            rb0 = *(const float4*)(pb0+ko);
            rb1 = *(const float4*)(pb1+ko);
        }
        mm16(As[t&1], Bs[t&1], m0, n0, acc);
        if (t+1 < nt){
            float* a2=As[(t+1)&1]; float* b2=Bs[(t+1)&1];
            sts4t(a2,k0,r0,ra0); sts4t(a2,k1,r1,ra1);
            sts4t(b2,k0,r0,rb0); sts4t(b2,k1,r1,rb1);
            __syncthreads();
        }
    }

    const float sc = 0.04419417382415922f;   // 1/sqrt(512)
    float* S = g_scores + (size_t)b*SLV*SLV;
    #pragma unroll
    for (int i=0;i<8;i++){
        size_t moff = (size_t)(bm+m0+i)*SLV + bn + n0;
        F2U u0,u1,u2,u3;
        u0.u=acc[i][0]; u1.u=acc[i][1]; u2.u=acc[i][2]; u3.u=acc[i][3];
        float4 mk0 = *(const float4*)(mask+moff);
        float4 mk1 = *(const float4*)(mask+moff+4);
        float4 o0, o1;
        o0.x = u0.f.x*sc + mk0.x; o0.y = u0.f.y*sc + mk0.y;
        o0.z = u1.f.x*sc + mk0.z; o0.w = u1.f.y*sc + mk0.w;
        o1.x = u2.f.x*sc + mk1.x; o1.y = u2.f.y*sc + mk1.y;
        o1.z = u3.f.x*sc + mk1.z; o1.w = u3.f.y*sc + mk1.w;
        *(float4*)(S+moff)   = o0;
        *(float4*)(S+moff+4) = o1;
    }
}

// ---------------- row softmax (in place), skipping fully-masked tiles ----------------
__global__ void __launch_bounds__(256)
softmax_kernel()
{
    const int row = blockIdx.x;            // b*SLV + q
    const int q = row & (SLV-1);
    const int qb = q >> 7;
    const int tid = threadIdx.x;
    __shared__ unsigned char fl[32];
    __shared__ float red[8];
    if (tid < 32) fl[tid] = g_flags[qb*32 + tid];
    __syncthreads();
    float* S = g_scores + (size_t)row*SLV;

    float vals[16];
    float mx = -3.402823466e38f;
    #pragma unroll
    for (int i=0;i<16;i++){
        int idx = i*256 + tid;
        float v = fl[idx>>7] ? -3.402823466e38f : S[idx];
        vals[i] = v; mx = fmaxf(mx, v);
    }
    #pragma unroll
    for (int o=16;o>0;o>>=1) mx = fmaxf(mx, __shfl_xor_sync(0xffffffffu, mx, o));
    if ((tid&31)==0) red[tid>>5] = mx;
    __syncthreads();
    float m = red[0];
    #pragma unroll
    for (int w=1;w<8;w++) m = fmaxf(m, red[w]);
    __syncthreads();

    float s = 0.f;
    #pragma unroll
    for (int i=0;i<16;i++){ float e = expf(vals[i]-m); vals[i]=e; s+=e; }
    #pragma unroll
    for (int o=16;o>0;o>>=1) s += __shfl_xor_sync(0xffffffffu, s, o);
    if ((tid&31)==0) red[tid>>5] = s;
    __syncthreads();
    float tot = 0.f;
    #pragma unroll
    for (int w=0;w<8;w++) tot += red[w];
    float inv = 1.0f/tot;
    #pragma unroll
    for (int i=0;i<16;i++){
        int idx = i*256 + tid;
        if (!fl[idx>>7]) S[idx] = vals[i]*inv;
    }
}

// ---------------- PV: h[b] = attn[b] @ xv[b]  (NN, skip masked k-tiles) ----------------
__global__ void __launch_bounds__(256,2)
pv_kernel()
{
    const int b = blockIdx.z, qb = blockIdx.y;
    const int bm = qb*128, bn = blockIdx.x*128;
    __shared__ __align__(16) float As[2][16*SA];
    __shared__ __align__(16) float Bs[2][16*SA];
    __shared__ int kbs[32];
    __shared__ int nkb_s;
    const int tid = threadIdx.x;
    if (tid==0){
        int c=0;
        for (int kb=0;kb<32;kb++) if (!g_flags[qb*32+kb]) kbs[c++]=kb;
        nkb_s = c;
    }
    __syncthreads();
    const int nt = nkb_s*8;
    const float* A = g_scores + (size_t)b*SLV*SLV;
    const float* B = g_xv + (size_t)b*SLV*DIMV;

    const int c0=tid, c1=tid+256;
    const int ar0=c0>>2, ak0=(c0&3)*4;
    const int ar1=c1>>2, ak1=(c1&3)*4;
    const int bk0=c0>>5, bn0=(c0&31)*4;
    const int bk1=c1>>5, bn1=(c1&31)*4;

    const int tx=tid&15, ty=tid>>4;
    const int m0=ty*8, n0=tx*8;

    unsigned long long acc[8][4];
    #pragma unroll
    for (int i=0;i<8;i++){
        #pragma unroll
        for (int j=0;j<4;j++) acc[i][j]=0ull;
    }

    int kt = kbs[0]*128;   // t=0
    float4 ra0 = *(const float4*)(A + (size_t)(bm+ar0)*SLV + kt+ak0);
    float4 ra1 = *(const float4*)(A + (size_t)(bm+ar1)*SLV + kt+ak1);
    float4 rb0 = *(const float4*)(B + (size_t)(kt+bk0)*DIMV + bn+bn0);
    float4 rb1 = *(const float4*)(B + (size_t)(kt+bk1)*DIMV + bn+bn1);
    sts4t(As[0],ak0,ar0,ra0); sts4t(As[0],ak1,ar1,ra1);
    *(float4*)&Bs[0][bk0*SA+bn0]=rb0; *(float4*)&Bs[0][bk1*SA+bn1]=rb1;
    __syncthreads();

    for (int t=0; t<nt; t++){
        if (t+1 < nt){
            int t2 = t+1;
            int k2 = kbs[t2>>3]*128 + (t2&7)*16;
            ra0 = *(const float4*)(A + (size_t)(bm+ar0)*SLV + k2+ak0);
            ra1 = *(const float4*)(A + (size_t)(bm+ar1)*SLV + k2+ak1);
            rb0 = *(const float4*)(B + (size_t)(k2+bk0)*DIMV + bn+bn0);
            rb1 = *(const float4*)(B + (size_t)(k2+bk1)*DIMV + bn+bn1);
        }
        mm16(As[t&1], Bs[t&1], m0, n0, acc);
        if (t+1 < nt){
            int bb=(t+1)&1;
            sts4t(As[bb],ak0,ar0,ra0); sts4t(As[bb],ak1,ar1,ra1);
            *(float4*)&Bs[bb][bk0*SA+bn0]=rb0; *(float4*)&Bs[bb][bk1*SA+bn1]=rb1;
            __syncthreads();
        }
    }

    #pragma unroll
    for (int i=0;i<8;i++){
        size_t off = (size_t)(b*SLV + bm+m0+i)*DIMV + bn + n0;
        F2U u0,u1,u2,u3;
        u0.u=acc[i][0]; u1.u=acc[i][1]; u2.u=acc[i][2]; u3.u=acc[i][3];
        float4 o0 = make_float4(u0.f.x,u0.f.y,u1.f.x,u1.f.y);
        float4 o1 = make_float4(u2.f.x,u2.f.y,u3.f.x,u3.f.y);
        *(float4*)(g_h+off)=o0; *(float4*)(g_h+off+4)=o1;
    }
}

// ---------------- launch ----------------
extern "C" void kernel_launch(void* const* d_in, const int* in_sizes, int n_in,
                              void* d_out, int out_size) {
    (void)in_sizes; (void)n_in; (void)out_size;
    const float* x    = (const float*)d_in[0];
    const float* mask = (const float*)d_in[1];
    float* out = (float*)d_out;

    float *Wk,*Wv,*Wo,*W1,*W2,*xk,*xv,*h,*hres,*ff1;
    cudaGetSymbolAddress((void**)&Wk,   g_Wk);
    cudaGetSymbolAddress((void**)&Wv,   g_Wv);
    cudaGetSymbolAddress((void**)&Wo,   g_Wo);
    cudaGetSymbolAddress((void**)&W1,   g_W1);
    cudaGetSymbolAddress((void**)&W2,   g_W2);
    cudaGetSymbolAddress((void**)&xk,   g_xk);
    cudaGetSymbolAddress((void**)&xv,   g_xv);
    cudaGetSymbolAddress((void**)&h,    g_h);
    cudaGetSymbolAddress((void**)&hres, g_hres);
    cudaGetSymbolAddress((void**)&ff1,  g_ff1);

    dim3 blk(256);

    make_w_kernel<<<(DIMV*DIMV+255)/256, blk>>>((const float*)d_in[2],(const float*)d_in[3],(const float*)d_in[4], Wk, DIMV*DIMV);
    make_w_kernel<<<(DIMV*DIMV+255)/256, blk>>>((const float*)d_in[5],(const float*)d_in[6],(const float*)d_in[7], Wv, DIMV*DIMV);
    make_w_kernel<<<(DIMV*DIMV+255)/256, blk>>>((const float*)d_in[8],(const float*)d_in[9],(const float*)d_in[10], Wo, DIMV*DIMV);
    make_w_kernel<<<(HIDV*DIMV+255)/256, blk>>>((const float*)d_in[11],(const float*)d_in[12],(const float*)d_in[13], W1, HIDV*DIMV);
    make_w_kernel<<<(DIMV*HIDV+255)/256, blk>>>((const float*)d_in[14],(const float*)d_in[15],(const float*)d_in[16], W2, DIMV*HIDV);

    // xk = x @ Wk^T ; xv = x @ Wv^T
    gemm_nt_kernel<<<dim3(DIMV/128, TOK/128), blk>>>(x, Wk, xk, nullptr, TOK, DIMV, DIMV, 0);
    gemm_nt_kernel<<<dim3(DIMV/128, TOK/128), blk>>>(x, Wv, xv, nullptr, TOK, DIMV, DIMV, 0);

    // causal tile flags from mask
    flags_kernel<<<dim3(32,32), blk>>>(mask);

    // scores + mask, softmax, attn @ xv
    scores_kernel<<<dim3(32,32,NBATCH), blk>>>(x, mask);
    softmax_kernel<<<TOK, blk>>>();
    pv_kernel<<<dim3(DIMV/128, SLV/128, NBATCH), blk>>>();

    // h_res = x + h @ Wo^T
    gemm_nt_kernel<<<dim3(DIMV/128, TOK/128), blk>>>(h, Wo, hres, x, TOK, DIMV, DIMV, 1);
    // ff1 = relu(h_res @ W1^T)
    gemm_nt_kernel<<<dim3(HIDV/128, TOK/128), blk>>>(hres, W1, ff1, nullptr, TOK, HIDV, DIMV, 2);
    // out = h_res + ff1 @ W2^T
    gemm_nt_kernel<<<dim3(DIMV/128, TOK/128), blk>>>(ff1, W2, out, hres, TOK, DIMV, HIDV, 1);
}

// round 11
// speedup vs baseline: 1.0011x; 1.0011x over previous
#include <cuda_runtime.h>
#include <math.h>

#define DIMV 512
#define HIDV 2048
#define NBATCH 4
#define SLV 4096
#define TOK (NBATCH*SLV)          // 16384
#define SA 132                    // smem row stride (128 + 4 pad), 132*4B % 16 == 0

// ---------------- scratch (device globals: no allocation allowed) ----------------
__device__ float g_Wk[DIMV*DIMV];
__device__ float g_Wv[DIMV*DIMV];
__device__ float g_Wo[DIMV*DIMV];
__device__ float g_W1[HIDV*DIMV];
__device__ float g_W2[DIMV*HIDV];
__device__ float g_xk[TOK*DIMV];
__device__ float g_xv[TOK*DIMV];
__device__ float g_h[TOK*DIMV];
__device__ float g_hres[TOK*DIMV];
__device__ float g_ff1[TOK*HIDV];                 // 33.5M floats
__device__ float g_scores[NBATCH*SLV*SLV];        // 67.1M floats (268 MB)
__device__ unsigned char g_flags[32*32];          // 1 = tile fully masked (<= -1e8)

// ---------------- f32x2 helpers (Blackwell packed fp32 FMA) ----------------
__device__ __forceinline__ void ffma2(unsigned long long &d, unsigned long long a, unsigned long long b){
    asm("fma.rn.f32x2 %0, %1, %2, %0;" : "+l"(d) : "l"(a), "l"(b));
}
__device__ __forceinline__ unsigned long long pk2(float x){
    unsigned long long r; asm("mov.b64 %0, {%1, %1};" : "=l"(r) : "f"(x)); return r;
}
union F2U { unsigned long long u; float2 f; };

// transpose-store a float4 (4 consecutive k) of one row into As[k][m]
__device__ __forceinline__ void sts4t(float* s, int k, int m, float4 v){
    s[(k+0)*SA+m]=v.x; s[(k+1)*SA+m]=v.y; s[(k+2)*SA+m]=v.z; s[(k+3)*SA+m]=v.w;
}

// 16-step inner product on one smem tile pair; acc pairs along n (low lane = even col)
__device__ __forceinline__ void mm16(const float* __restrict__ As, const float* __restrict__ Bs,
                                     int m0, int n0, unsigned long long (&acc)[8][4]){
    #pragma unroll
    for (int kk=0; kk<16; kk++){
        const float* ar = As + kk*SA + m0;
        float4 a0 = *(const float4*)(ar);
        float4 a1 = *(const float4*)(ar+4);
        const float* br = Bs + kk*SA + n0;
        ulonglong2 q0 = *(const ulonglong2*)(br);
        ulonglong2 q1 = *(const ulonglong2*)(br+4);
        unsigned long long b0=q0.x, b1=q0.y, b2=q1.x, b3=q1.y;
        unsigned long long a;
        a=pk2(a0.x); ffma2(acc[0][0],a,b0); ffma2(acc[0][1],a,b1); ffma2(acc[0][2],a,b2); ffma2(acc[0][3],a,b3);
        a=pk2(a0.y); ffma2(acc[1][0],a,b0); ffma2(acc[1][1],a,b1); ffma2(acc[1][2],a,b2); ffma2(acc[1][3],a,b3);
        a=pk2(a0.z); ffma2(acc[2][0],a,b0); ffma2(acc[2][1],a,b1); ffma2(acc[2][2],a,b2); ffma2(acc[2][3],a,b3);
        a=pk2(a0.w); ffma2(acc[3][0],a,b0); ffma2(acc[3][1],a,b1); ffma2(acc[3][2],a,b2); ffma2(acc[3][3],a,b3);
        a=pk2(a1.x); ffma2(acc[4][0],a,b0); ffma2(acc[4][1],a,b1); ffma2(acc[4][2],a,b2); ffma2(acc[4][3],a,b3);
        a=pk2(a1.y); ffma2(acc[5][0],a,b0); ffma2(acc[5][1],a,b1); ffma2(acc[5][2],a,b2); ffma2(acc[5][3],a,b3);
        a=pk2(a1.z); ffma2(acc[6][0],a,b0); ffma2(acc[6][1],a,b1); ffma2(acc[6][2],a,b2); ffma2(acc[6][3],a,b3);
        a=pk2(a1.w); ffma2(acc[7][0],a,b0); ffma2(acc[7][1],a,b1); ffma2(acc[7][2],a,b2); ffma2(acc[7][3],a,b3);
    }
}

// ---------------- weight materialization: W = mu + exp(ls)*eps ----------------
__global__ void make_w_kernel(const float* __restrict__ mu, const float* __restrict__ ls,
                              const float* __restrict__ eps, float* __restrict__ w, int n){
    int i = blockIdx.x*256 + threadIdx.x;
    if (i < n) w[i] = fmaf(expf(ls[i]), eps[i], mu[i]);
}

// ---------------- flags: 1 if whole 128x128 mask tile <= -1e8 ----------------
__global__ void flags_kernel(const float* __restrict__ mask){
    int qb=blockIdx.y, kb=blockIdx.x, tid=threadIdx.x;
    int any = 0;
    #pragma unroll 4
    for (int i=0;i<64;i++){
        int idx=i*256+tid; int r=idx>>7, c=idx&127;
        float v = mask[(size_t)(qb*128+r)*SLV + kb*128+c];
        any |= (v > -1e8f) ? 1 : 0;
    }
    int a = __syncthreads_or(any);
    if (tid==0) g_flags[qb*32+kb] = (a==0) ? 1 : 0;
}

// ---------------- generic NT GEMM: C[M,N] = A[M,K] * B[N,K]^T (+epilogue) ----------------
// epi: 0 = none, 1 = C += aux (same layout), 2 = relu
__global__ void __launch_bounds__(256,2)
gemm_nt_kernel(const float* __restrict__ A, const float* __restrict__ B,
               float* __restrict__ C, const float* __restrict__ aux,
               int M, int N, int K, int epi)
{
    (void)M;
    __shared__ __align__(16) float As[2][16*SA];
    __shared__ __align__(16) float Bs[2][16*SA];
    const int tid = threadIdx.x;
    const int bm = blockIdx.y*128;
    const int bn = blockIdx.x*128;

    const int c0=tid, c1=tid+256;
    const int r0=c0>>2, k0=(c0&3)*4;
    const int r1=c1>>2, k1=(c1&3)*4;
    const float* pa0 = A + (size_t)(bm+r0)*K + k0;
    const float* pa1 = A + (size_t)(bm+r1)*K + k1;
    const float* pb0 = B + (size_t)(bn+r0)*K + k0;
    const float* pb1 = B + (size_t)(bn+r1)*K + k1;

    const int tx=tid&15, ty=tid>>4;
    const int m0=ty*8, n0=tx*8;

    unsigned long long acc[8][4];
    #pragma unroll
    for (int i=0;i<8;i++){
        #pragma unroll
        for (int j=0;j<4;j++) acc[i][j]=0ull;
    }

    const int nt = K>>4;
    float4 ra0 = *(const float4*)pa0;
    float4 ra1 = *(const float4*)pa1;
    float4 rb0 = *(const float4*)pb0;
    float4 rb1 = *(const float4*)pb1;
    sts4t(As[0],k0,r0,ra0); sts4t(As[0],k1,r1,ra1);
    sts4t(Bs[0],k0,r0,rb0); sts4t(Bs[0],k1,r1,rb1);
    __syncthreads();

    for (int t=0; t<nt; t++){
        if (t+1 < nt){
            int ko=(t+1)*16;
            ra0 = *(const float4*)(pa0+ko);
            ra1 = *(const float4*)(pa1+ko);
            rb0 = *(const float4*)(pb0+ko);
            rb1 = *(const float4*)(pb1+ko);
        }
        mm16(As[t&1], Bs[t&1], m0, n0, acc);
        if (t+1 < nt){
            float* a2=As[(t+1)&1]; float* b2=Bs[(t+1)&1];
            sts4t(a2,k0,r0,ra0); sts4t(a2,k1,r1,ra1);
            sts4t(b2,k0,r0,rb0); sts4t(b2,k1,r1,rb1);
            __syncthreads();
        }
    }

    #pragma unroll
    for (int i=0;i<8;i++){
        size_t off = (size_t)(bm+m0+i)*N + bn + n0;
        F2U u0,u1,u2,u3;
        u0.u=acc[i][0]; u1.u=acc[i][1]; u2.u=acc[i][2]; u3.u=acc[i][3];
        float4 o0 = make_float4(u0.f.x,u0.f.y,u1.f.x,u1.f.y);
        float4 o1 = make_float4(u2.f.x,u2.f.y,u3.f.x,u3.f.y);
        if (epi==1){
            float4 x0 = *(const float4*)(aux+off);
            float4 x1 = *(const float4*)(aux+off+4);
            o0.x+=x0.x; o0.y+=x0.y; o0.z+=x0.z; o0.w+=x0.w;
            o1.x+=x1.x; o1.y+=x1.y; o1.z+=x1.z; o1.w+=x1.w;
        } else if (epi==2){
            o0.x=fmaxf(o0.x,0.f); o0.y=fmaxf(o0.y,0.f); o0.z=fmaxf(o0.z,0.f); o0.w=fmaxf(o0.w,0.f);
            o1.x=fmaxf(o1.x,0.f); o1.y=fmaxf(o1.y,0.f); o1.z=fmaxf(o1.z,0.f); o1.w=fmaxf(o1.w,0.f);
        }
        *(float4*)(C+off)=o0; *(float4*)(C+off+4)=o1;
    }
}

// ---------------- scores: S[b] = (x[b] @ xk[b]^T)/sqrt(D) + mask, skip fully-masked tiles --------
__global__ void __launch_bounds__(256,2)
scores_kernel(const float* __restrict__ x, const float* __restrict__ mask)
{
    const int b = blockIdx.z, qb=blockIdx.y, kb=blockIdx.x;
    if (g_flags[qb*32+kb]) return;
    const float* A = x   + (size_t)b*SLV*DIMV;
    const float* B = g_xk + (size_t)b*SLV*DIMV;

    __shared__ __align__(16) float As[2][16*SA];
    __shared__ __align__(16) float Bs[2][16*SA];
    const int tid = threadIdx.x;
    const int bm = qb*128, bn = kb*128;

    const int c0=tid, c1=tid+256;
    const int r0=c0>>2, k0=(c0&3)*4;
    const int r1=c1>>2, k1=(c1&3)*4;
    const float* pa0 = A + (size_t)(bm+r0)*DIMV + k0;
    const float* pa1 = A + (size_t)(bm+r1)*DIMV + k1;
    const float* pb0 = B + (size_t)(bn+r0)*DIMV + k0;
    const float* pb1 = B + (size_t)(bn+r1)*DIMV + k1;

    const int tx=tid&15, ty=tid>>4;
    const int m0=ty*8, n0=tx*8;

    unsigned long long acc[8][4];
    #pragma unroll
    for (int i=0;i<8;i++){
        #pragma unroll
        for (int j=0;j<4;j++) acc[i][j]=0ull;
    }

    const int nt = DIMV>>4;   // 32
    float4 ra0 = *(const float4*)pa0;
    float4 ra1 = *(const float4*)pa1;
    float4 rb0 = *(const float4*)pb0;
    float4 rb1 = *(const float4*)pb1;
    sts4t(As[0],k0,r0,ra0); sts4t(As[0],k1,r1,ra1);
    sts4t(Bs[0],k0,r0,rb0); sts4t(Bs[0],k1,r1,rb1);
    __syncthreads();

    for (int t=0; t<nt; t++){
        if (t+1 < nt){
            int ko=(t+1)*16;
            ra0 = *(const float4*)(pa0+ko);
            ra1 = *(const float4*)(pa1+ko);
            rb0 = *(const float4*)(pb0+ko);
            rb1 = *(const float4*)(pb1+ko);
        }
        mm16(As[t&1], Bs[t&1], m0, n0, acc);
        if (t+1 < nt){
            float* a2=As[(t+1)&1]; float* b2=Bs[(t+1)&1];
            sts4t(a2,k0,r0,ra0); sts4t(a2,k1,r1,ra1);
            sts4t(b2,k0,r0,rb0); sts4t(b2,k1,r1,rb1);
            __syncthreads();
        }
    }

    const float sc = 0.04419417382415922f;   // 1/sqrt(512)
    float* S = g_scores + (size_t)b*SLV*SLV;
    #pragma unroll
    for (int i=0;i<8;i++){
        size_t moff = (size_t)(bm+m0+i)*SLV + bn + n0;
        F2U u0,u1,u2,u3;
        u0.u=acc[i][0]; u1.u=acc[i][1]; u2.u=acc[i][2]; u3.u=acc[i][3];
        float4 mk0 = *(const float4*)(mask+moff);
        float4 mk1 = *(const float4*)(mask+moff+4);
        float4 o0, o1;
        o0.x = u0.f.x*sc + mk0.x; o0.y = u0.f.y*sc + mk0.y;
        o0.z = u1.f.x*sc + mk0.z; o0.w = u1.f.y*sc + mk0.w;
        o1.x = u2.f.x*sc + mk1.x; o1.y = u2.f.y*sc + mk1.y;
        o1.z = u3.f.x*sc + mk1.z; o1.w = u3.f.y*sc + mk1.w;
        *(float4*)(S+moff)   = o0;
        *(float4*)(S+moff+4) = o1;
    }
}

// ---------------- row softmax (in place), skipping fully-masked tiles ----------------
__global__ void __launch_bounds__(256)
softmax_kernel()
{
    const int row = blockIdx.x;            // b*SLV + q
    const int q = row & (SLV-1);
    const int qb = q >> 7;
    const int tid = threadIdx.x;
    __shared__ unsigned char fl[32];
    __shared__ float red[8];
    if (tid < 32) fl[tid] = g_flags[qb*32 + tid];
    __syncthreads();
    float* S = g_scores + (size_t)row*SLV;

    float vals[16];
    float mx = -3.402823466e38f;
    #pragma unroll
    for (int i=0;i<16;i++){
        int idx = i*256 + tid;
        float v = fl[idx>>7] ? -3.402823466e38f : S[idx];
        vals[i] = v; mx = fmaxf(mx, v);
    }
    #pragma unroll
    for (int o=16;o>0;o>>=1) mx = fmaxf(mx, __shfl_xor_sync(0xffffffffu, mx, o));
    if ((tid&31)==0) red[tid>>5] = mx;
    __syncthreads();
    float m = red[0];
    #pragma unroll
    for (int w=1;w<8;w++) m = fmaxf(m, red[w]);
    __syncthreads();

    float s = 0.f;
    #pragma unroll
    for (int i=0;i<16;i++){ float e = expf(vals[i]-m); vals[i]=e; s+=e; }
    #pragma unroll
    for (int o=16;o>0;o>>=1) s += __shfl_xor_sync(0xffffffffu, s, o);
    if ((tid&31)==0) red[tid>>5] = s;
    __syncthreads();
    float tot = 0.f;
    #pragma unroll
    for (int w=0;w<8;w++) tot += red[w];
    float inv = 1.0f/tot;
    #pragma unroll
    for (int i=0;i<16;i++){
        int idx = i*256 + tid;
        if (!fl[idx>>7]) S[idx] = vals[i]*inv;
    }
}

// ---------------- PV: h[b] = attn[b] @ xv[b]  (NN, skip masked k-tiles) ----------------
__global__ void __launch_bounds__(256,2)
pv_kernel()
{
    const int b = blockIdx.z, qb = blockIdx.y;
    const int bm = qb*128, bn = blockIdx.x*128;
    __shared__ __align__(16) float As[2][16*SA];
    __shared__ __align__(16) float Bs[2][16*SA];
    __shared__ int kbs[32];
    __shared__ int nkb_s;
    const int tid = threadIdx.x;
    if (tid==0){
        int c=0;
        for (int kb=0;kb<32;kb++) if (!g_flags[qb*32+kb]) kbs[c++]=kb;
        nkb_s = c;
    }
    __syncthreads();
    const int nt = nkb_s*8;
    const float* A = g_scores + (size_t)b*SLV*SLV;
    const float* B = g_xv + (size_t)b*SLV*DIMV;

    const int c0=tid, c1=tid+256;
    const int ar0=c0>>2, ak0=(c0&3)*4;
    const int ar1=c1>>2, ak1=(c1&3)*4;
    const int bk0=c0>>5, bn0=(c0&31)*4;
    const int bk1=c1>>5, bn1=(c1&31)*4;

    const int tx=tid&15, ty=tid>>4;
    const int m0=ty*8, n0=tx*8;

    unsigned long long acc[8][4];
    #pragma unroll
    for (int i=0;i<8;i++){
        #pragma unroll
        for (int j=0;j<4;j++) acc[i][j]=0ull;
    }

    int kt = kbs[0]*128;   // t=0
    float4 ra0 = *(const float4*)(A + (size_t)(bm+ar0)*SLV + kt+ak0);
    float4 ra1 = *(const float4*)(A + (size_t)(bm+ar1)*SLV + kt+ak1);
    float4 rb0 = *(const float4*)(B + (size_t)(kt+bk0)*DIMV + bn+bn0);
    float4 rb1 = *(const float4*)(B + (size_t)(kt+bk1)*DIMV + bn+bn1);
    sts4t(As[0],ak0,ar0,ra0); sts4t(As[0],ak1,ar1,ra1);
    *(float4*)&Bs[0][bk0*SA+bn0]=rb0; *(float4*)&Bs[0][bk1*SA+bn1]=rb1;
    __syncthreads();

    for (int t=0; t<nt; t++){
        if (t+1 < nt){
            int t2 = t+1;
            int k2 = kbs[t2>>3]*128 + (t2&7)*16;
            ra0 = *(const float4*)(A + (size_t)(bm+ar0)*SLV + k2+ak0);
            ra1 = *(const float4*)(A + (size_t)(bm+ar1)*SLV + k2+ak1);
            rb0 = *(const float4*)(B + (size_t)(k2+bk0)*DIMV + bn+bn0);
            rb1 = *(const float4*)(B + (size_t)(k2+bk1)*DIMV + bn+bn1);
        }
        mm16(As[t&1], Bs[t&1], m0, n0, acc);
        if (t+1 < nt){
            int bb=(t+1)&1;
            sts4t(As[bb],ak0,ar0,ra0); sts4t(As[bb],ak1,ar1,ra1);
            *(float4*)&Bs[bb][bk0*SA+bn0]=rb0; *(float4*)&Bs[bb][bk1*SA+bn1]=rb1;
            __syncthreads();
        }
    }

    #pragma unroll
    for (int i=0;i<8;i++){
        size_t off = (size_t)(b*SLV + bm+m0+i)*DIMV + bn + n0;
        F2U u0,u1,u2,u3;
        u0.u=acc[i][0]; u1.u=acc[i][1]; u2.u=acc[i][2]; u3.u=acc[i][3];
        float4 o0 = make_float4(u0.f.x,u0.f.y,u1.f.x,u1.f.y);
        float4 o1 = make_float4(u2.f.x,u2.f.y,u3.f.x,u3.f.y);
        *(float4*)(g_h+off)=o0; *(float4*)(g_h+off+4)=o1;
    }
}

// ---------------- launch ----------------
extern "C" void kernel_launch(void* const* d_in, const int* in_sizes, int n_in,
                              void* d_out, int out_size) {
    (void)in_sizes; (void)n_in; (void)out_size;
    const float* x    = (const float*)d_in[0];
    const float* mask = (const float*)d_in[1];
    float* out = (float*)d_out;

    float *Wk,*Wv,*Wo,*W1,*W2,*xk,*xv,*h,*hres,*ff1;
    cudaGetSymbolAddress((void**)&Wk,   g_Wk);
    cudaGetSymbolAddress((void**)&Wv,   g_Wv);
    cudaGetSymbolAddress((void**)&Wo,   g_Wo);
    cudaGetSymbolAddress((void**)&W1,   g_W1);
    cudaGetSymbolAddress((void**)&W2,   g_W2);
    cudaGetSymbolAddress((void**)&xk,   g_xk);
    cudaGetSymbolAddress((void**)&xv,   g_xv);
    cudaGetSymbolAddress((void**)&h,    g_h);
    cudaGetSymbolAddress((void**)&hres, g_hres);
    cudaGetSymbolAddress((void**)&ff1,  g_ff1);

    dim3 blk(256);

    make_w_kernel<<<(DIMV*DIMV+255)/256, blk>>>((const float*)d_in[2],(const float*)d_in[3],(const float*)d_in[4], Wk, DIMV*DIMV);
    make_w_kernel<<<(DIMV*DIMV+255)/256, blk>>>((const float*)d_in[5],(const float*)d_in[6],(const float*)d_in[7], Wv, DIMV*DIMV);
    make_w_kernel<<<(DIMV*DIMV+255)/256, blk>>>((const float*)d_in[8],(const float*)d_in[9],(const float*)d_in[10], Wo, DIMV*DIMV);
    make_w_kernel<<<(HIDV*DIMV+255)/256, blk>>>((const float*)d_in[11],(const float*)d_in[12],(const float*)d_in[13], W1, HIDV*DIMV);
    make_w_kernel<<<(DIMV*HIDV+255)/256, blk>>>((const float*)d_in[14],(const float*)d_in[15],(const float*)d_in[16], W2, DIMV*HIDV);

    // xk = x @ Wk^T ; xv = x @ Wv^T
    gemm_nt_kernel<<<dim3(DIMV/128, TOK/128), blk>>>(x, Wk, xk, nullptr, TOK, DIMV, DIMV, 0);
    gemm_nt_kernel<<<dim3(DIMV/128, TOK/128), blk>>>(x, Wv, xv, nullptr, TOK, DIMV, DIMV, 0);

    // causal tile flags from mask
    flags_kernel<<<dim3(32,32), blk>>>(mask);

    // scores + mask, softmax, attn @ xv
    scores_kernel<<<dim3(32,32,NBATCH), blk>>>(x, mask);
    softmax_kernel<<<TOK, blk>>>();
    pv_kernel<<<dim3(DIMV/128, SLV/128, NBATCH), blk>>>();

    // h_res = x + h @ Wo^T
    gemm_nt_kernel<<<dim3(DIMV/128, TOK/128), blk>>>(h, Wo, hres, x, TOK, DIMV, DIMV, 1);
    // ff1 = relu(h_res @ W1^T)
    gemm_nt_kernel<<<dim3(HIDV/128, TOK/128), blk>>>(hres, W1, ff1, nullptr, TOK, HIDV, DIMV, 2);
    // out = h_res + ff1 @ W2^T
    gemm_nt_kernel<<<dim3(DIMV/128, TOK/128), blk>>>(ff1, W2, out, hres, TOK, DIMV, HIDV, 1);
}

// round 13
// speedup vs baseline: 2.4451x; 2.4423x over previous
#include <cuda_runtime.h>
#include <cuda_bf16.h>
#include <math.h>

#define DIMV 512
#define HIDV 2048
#define NBATCH 4
#define SLV 4096
#define TOK (NBATCH*SLV)          // 16384

#if defined(__CUDA_ARCH_FEAT_SM103_ALL) || defined(__CUDA_ARCH_FEAT_SM100_ALL) || defined(__CUDA_ARCH_FEAT_SM110_ALL)
#define TC_OK 1
#else
#define TC_OK 0
#endif

// ---------------- scratch (device globals: no allocation allowed) ----------------
__device__ float g_Wk[DIMV*DIMV];
__device__ float g_Wv[DIMV*DIMV];
__device__ float g_Wo[DIMV*DIMV];
__device__ float g_W1[HIDV*DIMV];
__device__ float g_W2[DIMV*HIDV];
__device__ float g_xk[TOK*DIMV];
__device__ float g_xvT[NBATCH*DIMV*SLV];          // transposed V: [b][d][s]
__device__ float g_h[TOK*DIMV];
__device__ float g_hres[TOK*DIMV];
__device__ float g_ff1[TOK*HIDV];
__device__ float g_scores[(size_t)NBATCH*SLV*SLV];
__device__ unsigned char g_flags[32*32];          // 1 = tile fully masked

// ---------------- smem layout (dynamic) ----------------
// tc path: 3 stages x 64KB: [Ah 16K][Al 16K][Bh 16K][Bl 16K]
#define TILEB   16384
#define STAGEB  65536
#define TMEMP_OFF 196608
#define MB_OFF    196616          // 3 mbarriers x 8B
#define KL_OFF    196648          // 32 ints
#define NKB_OFF   196776
#define SMEM_REQ  197808          // includes 1KB alignment slack

__device__ __forceinline__ unsigned smem_u32(const void* p){
    unsigned a;
    asm("{ .reg .u64 t; cvta.to.shared.u64 t, %1; cvt.u32.u64 %0, t; }" : "=r"(a) : "l"(p));
    return a;
}

// ================= shared small kernels =================
__global__ void make_w_kernel(const float* __restrict__ mu, const float* __restrict__ ls,
                              const float* __restrict__ eps, float* __restrict__ w, int n){
    int i = blockIdx.x*256 + threadIdx.x;
    if (i < n) w[i] = fmaf(expf(ls[i]), eps[i], mu[i]);
}

__global__ void flags_kernel(const float* __restrict__ mask){
    int qb=blockIdx.y, kb=blockIdx.x, tid=threadIdx.x;
    int any = 0;
    #pragma unroll 4
    for (int i=0;i<64;i++){
        int idx=i*256+tid; int r=idx>>7, c=idx&127;
        float v = mask[(size_t)(qb*128+r)*SLV + kb*128+c];
        any |= (v > -1e8f) ? 1 : 0;
    }
    int a = __syncthreads_or(any);
    if (tid==0) g_flags[qb*32+kb] = (a==0) ? 1 : 0;
}

__global__ void __launch_bounds__(256)
softmax_kernel()
{
    const int row = blockIdx.x;            // b*SLV + q
    const int q = row & (SLV-1);
    const int qb = q >> 7;
    const int tid = threadIdx.x;
    __shared__ unsigned char fl[32];
    __shared__ float red[8];
    if (tid < 32) fl[tid] = g_flags[qb*32 + tid];
    __syncthreads();
    float* S = g_scores + (size_t)row*SLV;

    float vals[16];
    float mx = -3.402823466e38f;
    #pragma unroll
    for (int i=0;i<16;i++){
        int idx = i*256 + tid;
        float v = fl[idx>>7] ? -3.402823466e38f : S[idx];
        vals[i] = v; mx = fmaxf(mx, v);
    }
    #pragma unroll
    for (int o=16;o>0;o>>=1) mx = fmaxf(mx, __shfl_xor_sync(0xffffffffu, mx, o));
    if ((tid&31)==0) red[tid>>5] = mx;
    __syncthreads();
    float m = red[0];
    #pragma unroll
    for (int w=1;w<8;w++) m = fmaxf(m, red[w]);
    __syncthreads();

    float s = 0.f;
    #pragma unroll
    for (int i=0;i<16;i++){ float e = expf(vals[i]-m); vals[i]=e; s+=e; }
    #pragma unroll
    for (int o=16;o>0;o>>=1) s += __shfl_xor_sync(0xffffffffu, s, o);
    if ((tid&31)==0) red[tid>>5] = s;
    __syncthreads();
    float tot = 0.f;
    #pragma unroll
    for (int w=0;w<8;w++) tot += red[w];
    float inv = 1.0f/tot;
    #pragma unroll
    for (int i=0;i<16;i++){
        int idx = i*256 + tid;
        if (!fl[idx>>7]) S[idx] = vals[i]*inv;
    }
}

#if TC_OK
// =====================================================================
// ===================== tcgen05 path (sm_103a cubin) ==================
// =====================================================================
__device__ __forceinline__ unsigned elect1(){
    unsigned p;
    asm volatile("{ .reg .pred p; elect.sync _|p, 0xFFFFFFFF; selp.b32 %0, 1, 0, p; }" : "=r"(p));
    return p;
}
#define MBAR_INIT(a,c) asm volatile("mbarrier.init.shared.b64 [%0], %1;" :: "r"(a), "r"(c) : "memory")
#define MBAR_WAIT(addr, ph) do { \
    unsigned _d; \
    asm volatile("{ .reg .pred P; mbarrier.try_wait.parity.acquire.cta.shared::cta.b64 P, [%1], %2; selp.b32 %0,1,0,P; }" \
        : "=r"(_d) : "r"(addr), "r"(ph) : "memory"); \
    while(!_d){ \
        asm volatile("{ .reg .pred P; mbarrier.try_wait.parity.acquire.cta.shared::cta.b64 P, [%1], %2, 0x989680; selp.b32 %0,1,0,P; }" \
            : "=r"(_d) : "r"(addr), "r"(ph) : "memory"); \
    } \
} while(0)
#define TC_ALLOC(a,n)  asm volatile("tcgen05.alloc.cta_group::1.sync.aligned.shared::cta.b32 [%0], %1;" :: "r"(a), "r"(n) : "memory")
#define TC_RELINQ()    asm volatile("tcgen05.relinquish_alloc_permit.cta_group::1.sync.aligned;")
#define TC_DEALLOC(t,n) asm volatile("tcgen05.dealloc.cta_group::1.sync.aligned.b32 %0, %1;" :: "r"(t), "r"(n))
#define TC_COMMIT(a)   asm volatile("tcgen05.commit.cta_group::1.mbarrier::arrive::one.shared::cluster.b64 [%0];" :: "r"(a) : "memory")
#define TC_FENCE_AFTER() asm volatile("tcgen05.fence::after_thread_sync;" ::: "memory")
#define TC_WAIT_LD()   asm volatile("tcgen05.wait::ld.sync.aligned;" ::: "memory")
#define FENCE_ASYNC()  asm volatile("fence.proxy.async.shared::cta;" ::: "memory")
#define SW128(o) ((o) ^ (((o)>>3)&0x70))

#define LDX32(r, ta) \
    asm volatile("tcgen05.ld.sync.aligned.32x32b.x32.b32 " \
        "{%0, %1, %2, %3, %4, %5, %6, %7, %8, %9, %10, %11, %12, %13, %14, %15, " \
        " %16, %17, %18, %19, %20, %21, %22, %23, %24, %25, %26, %27, %28, %29, %30, %31}, [%32];" \
        : "=r"((r)[0]),  "=r"((r)[1]),  "=r"((r)[2]),  "=r"((r)[3]), \
          "=r"((r)[4]),  "=r"((r)[5]),  "=r"((r)[6]),  "=r"((r)[7]), \
          "=r"((r)[8]),  "=r"((r)[9]),  "=r"((r)[10]), "=r"((r)[11]), \
          "=r"((r)[12]), "=r"((r)[13]), "=r"((r)[14]), "=r"((r)[15]), \
          "=r"((r)[16]), "=r"((r)[17]), "=r"((r)[18]), "=r"((r)[19]), \
          "=r"((r)[20]), "=r"((r)[21]), "=r"((r)[22]), "=r"((r)[23]), \
          "=r"((r)[24]), "=r"((r)[25]), "=r"((r)[26]), "=r"((r)[27]), \
          "=r"((r)[28]), "=r"((r)[29]), "=r"((r)[30]), "=r"((r)[31]) \
        : "r"(ta))

// SMEM descriptor: K-major SW128, 128B rows (LBO=1, SBO=64), Blackwell v1
__device__ __forceinline__ unsigned long long mk_desc(unsigned addr){
    const unsigned long long base = (2ULL<<61) | (1ULL<<46) | (64ULL<<32) | (1ULL<<16);
    return base | (unsigned long long)((addr>>4)&0x3FFF);
}

// idesc kind::f16: dtype=F32, atype=BF16, btype=BF16, N=128, M=128
#define IDESC 0x8200490u

__device__ __forceinline__ void mma_ss(unsigned d, unsigned long long ad, unsigned long long bd, bool en){
    unsigned e = en ? 1u : 0u;
    asm volatile("{\n\t.reg .pred p;\n\tsetp.ne.u32 p, %4, 0;\n\t"
        "tcgen05.mma.cta_group::1.kind::f16 [%0], %1, %2, %3, {%5,%5,%5,%5}, p;\n\t}"
        :: "r"(d), "l"(ad), "l"(bd), "r"(IDESC), "r"(e), "r"(0u) : "memory");
}

__device__ __forceinline__ void issue_stage(unsigned tmem, unsigned sb, bool first){
    unsigned long long ah = mk_desc(sb);
    unsigned long long al = mk_desc(sb + TILEB);
    unsigned long long bh = mk_desc(sb + 2*TILEB);
    unsigned long long bl = mk_desc(sb + 3*TILEB);
    #pragma unroll
    for (int k=0;k<4;k++) mma_ss(tmem, ah+k*2, bh+k*2, !(first && k==0));
    #pragma unroll
    for (int k=0;k<4;k++) mma_ss(tmem, ah+k*2, bl+k*2, true);
    #pragma unroll
    for (int k=0;k<4;k++) mma_ss(tmem, al+k*2, bh+k*2, true);
}

// ---------------- fp32 -> (hi,lo) bf16 pair conversion ----------------
__device__ __forceinline__ void cvt_pair(float x0, float x1, unsigned &h, unsigned &l){
    union { __nv_bfloat162 b; unsigned u; } cv;
    cv.b = __floats2bfloat162_rn(x0, x1);      // .x (low 16) = x0, .y (high) = x1
    unsigned hu = cv.u;
    float f0 = __uint_as_float(hu << 16);
    float f1 = __uint_as_float(hu & 0xFFFF0000u);
    cv.b = __floats2bfloat162_rn(x0 - f0, x1 - f1);
    h = hu; l = cv.u;
}

// stage loader: one operand tile (128 rows x 64 cols fp32) -> hi/lo bf16 SW128 smem
__device__ __forceinline__ void load_conv(const float* __restrict__ P, size_t ld, int koff,
                                          char* dst_h, char* dst_l, int tid){
    int w = tid>>5, lane = tid&31;
    int rbase = w*16 + (lane>>4);
    int c = (lane&15)*4;
    #pragma unroll
    for (int i=0;i<8;i++){
        int r = rbase + i*2;
        float4 a = *(const float4*)(P + (size_t)r*ld + koff + c);
        unsigned h0,l0,h1,l1;
        cvt_pair(a.x, a.y, h0, l0);
        cvt_pair(a.z, a.w, h1, l1);
        unsigned off = SW128((unsigned)(r*128 + c*2));
        *(unsigned long long*)(dst_h+off) = ((unsigned long long)h1<<32) | h0;
        *(unsigned long long*)(dst_l+off) = ((unsigned long long)l1<<32) | l0;
    }
}

__device__ __forceinline__ void load_stage(const float* A, size_t lda, const float* B, size_t ldb,
                                           int koff, char* buf, int tid){
    load_conv(A, lda, koff, buf,           buf +   TILEB, tid);
    load_conv(B, ldb, koff, buf + 2*TILEB, buf + 3*TILEB, tid);
}

__device__ __forceinline__ int koff_of(const int* kl, int t){
    return kl ? (kl[t>>1]*128 + (t&1)*64) : (t<<6);
}

// ---------------- pipelined MMA core (3 smem stages) ----------------
__device__ __forceinline__ void gemm_core(const float* A, size_t lda, const float* B, size_t ldb,
                                          int nt, const int* kl,
                                          char* sm, unsigned smb, unsigned tmem){
    const int tid = threadIdx.x;
    const int wid = tid>>5;
    int ph[3] = {0,0,0};

    load_stage(A,lda,B,ldb, koff_of(kl,0), sm, tid);
    if (nt>1) load_stage(A,lda,B,ldb, koff_of(kl,1), sm + STAGEB, tid);
    FENCE_ASYNC();
    __syncthreads();

    for (int t=0; t<nt; t++){
        int b = t%3;
        if (wid==0 && elect1()){
            issue_stage(tmem, smb + b*STAGEB, t==0);
            TC_COMMIT(smb + MB_OFF + b*8);
        }
        int s = t+2;
        if (s < nt){
            int nb = s%3;
            if (s >= 3){ MBAR_WAIT(smb + MB_OFF + nb*8, ph[nb]); ph[nb]^=1; }
            load_stage(A,lda,B,ldb, koff_of(kl,s), sm + nb*STAGEB, tid);
            FENCE_ASYNC();
            __syncthreads();
        } else if (t == nt-1){
            MBAR_WAIT(smb + MB_OFF + b*8, ph[b]); ph[b]^=1;
            TC_FENCE_AFTER();
        }
    }
    __syncthreads();
}

__device__ __forceinline__ unsigned gemm_prologue(unsigned smb){
    const int tid = threadIdx.x;
    if (tid==0){
        MBAR_INIT(smb+MB_OFF,   1);
        MBAR_INIT(smb+MB_OFF+8, 1);
        MBAR_INIT(smb+MB_OFF+16,1);
    }
    if ((tid>>5)==0){ TC_ALLOC(smb+TMEMP_OFF, 128); TC_RELINQ(); }
    __syncthreads();
    unsigned tmem;
    asm volatile("ld.shared.b32 %0, [%1];" : "=r"(tmem) : "r"(smb+TMEMP_OFF));
    return tmem;
}

// ---------------- generic NT GEMM: C[M,N] = A[M,K] * B[N,K]^T ----------------
// EPI: 0 none, 1 add aux, 2 relu, 3 transposed store to xvT
template<int EPI>
__global__ void __launch_bounds__(256)
gemm_tc(const float* __restrict__ A, const float* __restrict__ B,
        float* __restrict__ C, const float* __restrict__ aux, int K, int N)
{
    extern __shared__ char sm_raw[];
    unsigned smb0 = smem_u32(sm_raw);
    unsigned smb = (smb0 + 1023) & ~1023u;
    char* sm = sm_raw + (smb - smb0);

    const int tid = threadIdx.x, wid = tid>>5, lane = tid&31;
    const int bm = blockIdx.y*128, bn = blockIdx.x*128;

    unsigned tmem = gemm_prologue(smb);
    gemm_core(A + (size_t)bm*K, K, B + (size_t)bn*K, K, K>>6, nullptr, sm, smb, tmem);

    const int band = wid&3;
    if (EPI != 3){
        const int m = bm + band*32 + lane;
        #pragma unroll
        for (int cc=0; cc<2; cc++){
            int c0 = (wid>>2)*64 + cc*32;
            unsigned rr[32];
            LDX32(rr, tmem + c0);
            TC_WAIT_LD();
            size_t off = (size_t)m*N + bn + c0;
            #pragma unroll
            for (int j=0;j<32;j+=4){
                float4 v = make_float4(__uint_as_float(rr[j]),   __uint_as_float(rr[j+1]),
                                       __uint_as_float(rr[j+2]), __uint_as_float(rr[j+3]));
                if (EPI==1){
                    float4 x = *(const float4*)(aux+off+j);
                    v.x+=x.x; v.y+=x.y; v.z+=x.z; v.w+=x.w;
                } else if (EPI==2){
                    v.x=fmaxf(v.x,0.f); v.y=fmaxf(v.y,0.f); v.z=fmaxf(v.z,0.f); v.w=fmaxf(v.w,0.f);
                }
                *(float4*)(C+off+j) = v;
            }
        }
    } else {
        // transposed store: C = xvT [b][d][s]   (32x36 padded smem transpose per warp)
        const int b = bm >> 12;
        const int s0 = (bm & 4095) + band*32;
        float* tb = (float*)(sm + wid*4608);   // 32 x 36 floats per warp (16B-aligned rows)
        #pragma unroll
        for (int cc=0; cc<2; cc++){
            int c0 = (wid>>2)*64 + cc*32;
            unsigned rr[32];
            LDX32(rr, tmem + c0);
            TC_WAIT_LD();
            #pragma unroll
            for (int j=0;j<32;j++) tb[j*36 + lane] = __uint_as_float(rr[j]);
            __syncwarp();
            size_t off = (size_t)b*DIMV*SLV + (size_t)(bn + c0 + lane)*SLV + s0;
            #pragma unroll
            for (int i=0;i<32;i+=4){
                float4 g = make_float4(tb[lane*36+i], tb[lane*36+i+1], tb[lane*36+i+2], tb[lane*36+i+3]);
                *(float4*)(C+off+i) = g;
            }
            __syncwarp();
        }
    }
    __syncthreads();
    if (wid==0) TC_DEALLOC(tmem, 128);
}

// ---------------- scores: S = (x @ xk^T)/sqrt(D) + mask, skip masked tiles ----------------
__global__ void __launch_bounds__(256)
scores_tc(const float* __restrict__ x, const float* __restrict__ mask)
{
    const int b = blockIdx.z, qb = blockIdx.y, kb = blockIdx.x;
    if (g_flags[qb*32+kb]) return;

    extern __shared__ char sm_raw[];
    unsigned smb0 = smem_u32(sm_raw);
    unsigned smb = (smb0 + 1023) & ~1023u;
    char* sm = sm_raw + (smb - smb0);

    const int tid = threadIdx.x, wid = tid>>5, lane = tid&31;
    const int bm = qb*128, bn = kb*128;
    const float* A = x    + (size_t)b*SLV*DIMV + (size_t)bm*DIMV;
    const float* B = g_xk + (size_t)b*SLV*DIMV + (size_t)bn*DIMV;

    unsigned tmem = gemm_prologue(smb);
    gemm_core(A, DIMV, B, DIMV, DIMV>>6, nullptr, sm, smb, tmem);

    const float sc = 0.04419417382415922f;
    float* S = g_scores + (size_t)b*SLV*SLV;
    const int m = bm + (wid&3)*32 + lane;
    #pragma unroll
    for (int cc=0; cc<2; cc++){
        int c0 = (wid>>2)*64 + cc*32;
        unsigned rr[32];
        LDX32(rr, tmem + c0);
        TC_WAIT_LD();
        size_t off = (size_t)m*SLV + bn + c0;
        #pragma unroll
        for (int j=0;j<32;j+=4){
            float4 mk = *(const float4*)(mask+off+j);
            float4 v;
            v.x = __uint_as_float(rr[j])  *sc + mk.x;
            v.y = __uint_as_float(rr[j+1])*sc + mk.y;
            v.z = __uint_as_float(rr[j+2])*sc + mk.z;
            v.w = __uint_as_float(rr[j+3])*sc + mk.w;
            *(float4*)(S+off+j) = v;
        }
    }
    __syncthreads();
    if (wid==0) TC_DEALLOC(tmem, 128);
}

// ---------------- PV: h = attn @ xv via xvT, skip masked k-tiles ----------------
__global__ void __launch_bounds__(256)
pv_tc()
{
    extern __shared__ char sm_raw[];
    unsigned smb0 = smem_u32(sm_raw);
    unsigned smb = (smb0 + 1023) & ~1023u;
    char* sm = sm_raw + (smb - smb0);

    const int b = blockIdx.z, qb = blockIdx.y;
    const int bm = qb*128, bn = blockIdx.x*128;
    const int tid = threadIdx.x, wid = tid>>5, lane = tid&31;

    int* kl = (int*)(sm + KL_OFF);
    int* nkb_p = (int*)(sm + NKB_OFF);
    if (tid==0){
        MBAR_INIT(smb+MB_OFF,   1);
        MBAR_INIT(smb+MB_OFF+8, 1);
        MBAR_INIT(smb+MB_OFF+16,1);
        int c=0;
        for (int kb=0;kb<32;kb++) if (!g_flags[qb*32+kb]) kl[c++]=kb;
        *nkb_p = c;
    }
    if (wid==0){ TC_ALLOC(smb+TMEMP_OFF, 128); TC_RELINQ(); }
    __syncthreads();
    unsigned tmem;
    asm volatile("ld.shared.b32 %0, [%1];" : "=r"(tmem) : "r"(smb+TMEMP_OFF));
    const int nt = (*nkb_p)*2;

    const float* A = g_scores + (size_t)b*SLV*SLV + (size_t)bm*SLV;
    const float* B = g_xvT   + (size_t)b*DIMV*SLV + (size_t)bn*SLV;
    gemm_core(A, SLV, B, SLV, nt, kl, sm, smb, tmem);

    const int m = bm + (wid&3)*32 + lane;
    #pragma unroll
    for (int cc=0; cc<2; cc++){
        int c0 = (wid>>2)*64 + cc*32;
        unsigned rr[32];
        LDX32(rr, tmem + c0);
        TC_WAIT_LD();
        size_t off = (size_t)(b*SLV + m)*DIMV + bn + c0;
        #pragma unroll
        for (int j=0;j<32;j+=4){
            float4 v = make_float4(__uint_as_float(rr[j]),   __uint_as_float(rr[j+1]),
                                   __uint_as_float(rr[j+2]), __uint_as_float(rr[j+3]));
            *(float4*)(g_h+off+j) = v;
        }
    }
    __syncthreads();
    if (wid==0) TC_DEALLOC(tmem, 128);
}

#else
// =====================================================================
// ============ fallback path (compute_103 PTX, f32x2 SIMT) ============
// =====================================================================
#define SA 132

__device__ __forceinline__ void ffma2(unsigned long long &d, unsigned long long a, unsigned long long b){
    asm("fma.rn.f32x2 %0, %1, %2, %0;" : "+l"(d) : "l"(a), "l"(b));
}
__device__ __forceinline__ unsigned long long pk2(float x){
    unsigned long long r; asm("mov.b64 %0, {%1, %1};" : "=l"(r) : "f"(x)); return r;
}
union F2U { unsigned long long u; float2 f; };

__device__ __forceinline__ void sts4t(float* s, int k, int m, float4 v){
    s[(k+0)*SA+m]=v.x; s[(k+1)*SA+m]=v.y; s[(k+2)*SA+m]=v.z; s[(k+3)*SA+m]=v.w;
}

__device__ __forceinline__ void mm16(const float* __restrict__ As, const float* __restrict__ Bs,
                                     int m0, int n0, unsigned long long (&acc)[8][4]){
    #pragma unroll
    for (int kk=0; kk<16; kk++){
        const float* ar = As + kk*SA + m0;
        float4 a0 = *(const float4*)(ar);
        float4 a1 = *(const float4*)(ar+4);
        const float* br = Bs + kk*SA + n0;
        ulonglong2 q0 = *(const ulonglong2*)(br);
        ulonglong2 q1 = *(const ulonglong2*)(br+4);
        unsigned long long b0=q0.x, b1=q0.y, b2=q1.x, b3=q1.y;
        unsigned long long a;
        a=pk2(a0.x); ffma2(acc[0][0],a,b0); ffma2(acc[0][1],a,b1); ffma2(acc[0][2],a,b2); ffma2(acc[0][3],a,b3);
        a=pk2(a0.y); ffma2(acc[1][0],a,b0); ffma2(acc[1][1],a,b1); ffma2(acc[1][2],a,b2); ffma2(acc[1][3],a,b3);
        a=pk2(a0.z); ffma2(acc[2][0],a,b0); ffma2(acc[2][1],a,b1); ffma2(acc[2][2],a,b2); ffma2(acc[2][3],a,b3);
        a=pk2(a0.w); ffma2(acc[3][0],a,b0); ffma2(acc[3][1],a,b1); ffma2(acc[3][2],a,b2); ffma2(acc[3][3],a,b3);
        a=pk2(a1.x); ffma2(acc[4][0],a,b0); ffma2(acc[4][1],a,b1); ffma2(acc[4][2],a,b2); ffma2(acc[4][3],a,b3);
        a=pk2(a1.y); ffma2(acc[5][0],a,b0); ffma2(acc[5][1],a,b1); ffma2(acc[5][2],a,b2); ffma2(acc[5][3],a,b3);
        a=pk2(a1.z); ffma2(acc[6][0],a,b0); ffma2(acc[6][1],a,b1); ffma2(acc[6][2],a,b2); ffma2(acc[6][3],a,b3);
        a=pk2(a1.w); ffma2(acc[7][0],a,b0); ffma2(acc[7][1],a,b1); ffma2(acc[7][2],a,b2); ffma2(acc[7][3],a,b3);
    }
}

template<int EPI>
__global__ void __launch_bounds__(256)
gemm_tc(const float* __restrict__ A, const float* __restrict__ B,
        float* __restrict__ C, const float* __restrict__ aux, int K, int N)
{
    extern __shared__ char sm_raw[];
    float* Asb[2]; float* Bsb[2];
    Asb[0]=(float*)sm_raw; Asb[1]=Asb[0]+16*SA; Bsb[0]=Asb[1]+16*SA; Bsb[1]=Bsb[0]+16*SA;
    const int tid = threadIdx.x;
    const int bm = blockIdx.y*128, bn = blockIdx.x*128;

    const int c0=tid, c1=tid+256;
    const int r0=c0>>2, k0=(c0&3)*4;
    const int r1=c1>>2, k1=(c1&3)*4;
    const float* pa0 = A + (size_t)(bm+r0)*K + k0;
    const float* pa1 = A + (size_t)(bm+r1)*K + k1;
    const float* pb0 = B + (size_t)(bn+r0)*K + k0;
    const float* pb1 = B + (size_t)(bn+r1)*K + k1;

    const int tx=tid&15, ty=tid>>4;
    const int m0=ty*8, n0=tx*8;

    unsigned long long acc[8][4];
    #pragma unroll
    for (int i=0;i<8;i++){ acc[i][0]=acc[i][1]=acc[i][2]=acc[i][3]=0ull; }

    const int nt = K>>4;
    float4 ra0 = *(const float4*)pa0;
    float4 ra1 = *(const float4*)pa1;
    float4 rb0 = *(const float4*)pb0;
    float4 rb1 = *(const float4*)pb1;
    sts4t(Asb[0],k0,r0,ra0); sts4t(Asb[0],k1,r1,ra1);
    sts4t(Bsb[0],k0,r0,rb0); sts4t(Bsb[0],k1,r1,rb1);
    __syncthreads();

    for (int t=0; t<nt; t++){
        if (t+1 < nt){
            int ko=(t+1)*16;
            ra0 = *(const float4*)(pa0+ko);
            ra1 = *(const float4*)(pa1+ko);
            rb0 = *(const float4*)(pb0+ko);
            rb1 = *(const float4*)(pb1+ko);
        }
        mm16(Asb[t&1], Bsb[t&1], m0, n0, acc);
        if (t+1 < nt){
            float* a2=Asb[(t+1)&1]; float* b2=Bsb[(t+1)&1];
            sts4t(a2,k0,r0,ra0); sts4t(a2,k1,r1,ra1);
            sts4t(b2,k0,r0,rb0); sts4t(b2,k1,r1,rb1);
            __syncthreads();
        }
    }

    #pragma unroll
    for (int i=0;i<8;i++){
        F2U u0,u1,u2,u3;
        u0.u=acc[i][0]; u1.u=acc[i][1]; u2.u=acc[i][2]; u3.u=acc[i][3];
        float vv[8] = {u0.f.x,u0.f.y,u1.f.x,u1.f.y,u2.f.x,u2.f.y,u3.f.x,u3.f.y};
        if (EPI==3){
            int b = bm >> 12; int s = (bm & 4095) + m0 + i;
            #pragma unroll
            for (int j=0;j<8;j++)
                C[(size_t)b*DIMV*SLV + (size_t)(bn+n0+j)*SLV + s] = vv[j];
        } else {
            size_t off = (size_t)(bm+m0+i)*N + bn + n0;
            #pragma unroll
            for (int j=0;j<8;j++){
                float v = vv[j];
                if (EPI==1) v += aux[off+j];
                else if (EPI==2) v = fmaxf(v,0.f);
                C[off+j] = v;
            }
        }
    }
}

__global__ void __launch_bounds__(256)
scores_tc(const float* __restrict__ x, const float* __restrict__ mask)
{
    const int b = blockIdx.z, qb=blockIdx.y, kb=blockIdx.x;
    if (g_flags[qb*32+kb]) return;
    extern __shared__ char sm_raw[];
    float* Asb[2]; float* Bsb[2];
    Asb[0]=(float*)sm_raw; Asb[1]=Asb[0]+16*SA; Bsb[0]=Asb[1]+16*SA; Bsb[1]=Bsb[0]+16*SA;
    const float* A = x    + (size_t)b*SLV*DIMV;
    const float* B = g_xk + (size_t)b*SLV*DIMV;
    const int tid = threadIdx.x;
    const int bm = qb*128, bn = kb*128;

    const int c0=tid, c1=tid+256;
    const int r0=c0>>2, k0=(c0&3)*4;
    const int r1=c1>>2, k1=(c1&3)*4;
    const float* pa0 = A + (size_t)(bm+r0)*DIMV + k0;
    const float* pa1 = A + (size_t)(bm+r1)*DIMV + k1;
    const float* pb0 = B + (size_t)(bn+r0)*DIMV + k0;
    const float* pb1 = B + (size_t)(bn+r1)*DIMV + k1;

    const int tx=tid&15, ty=tid>>4;
    const int m0=ty*8, n0=tx*8;

    unsigned long long acc[8][4];
    #pragma unroll
    for (int i=0;i<8;i++){ acc[i][0]=acc[i][1]=acc[i][2]=acc[i][3]=0ull; }

    const int nt = DIMV>>4;
    float4 ra0 = *(const float4*)pa0;
    float4 ra1 = *(const float4*)pa1;
    float4 rb0 = *(const float4*)pb0;
    float4 rb1 = *(const float4*)pb1;
    sts4t(Asb[0],k0,r0,ra0); sts4t(Asb[0],k1,r1,ra1);
    sts4t(Bsb[0],k0,r0,rb0); sts4t(Bsb[0],k1,r1,rb1);
    __syncthreads();

    for (int t=0; t<nt; t++){
        if (t+1 < nt){
            int ko=(t+1)*16;
            ra0 = *(const float4*)(pa0+ko);
            ra1 = *(const float4*)(pa1+ko);
            rb0 = *(const float4*)(pb0+ko);
            rb1 = *(const float4*)(pb1+ko);
        }
        mm16(Asb[t&1], Bsb[t&1], m0, n0, acc);
        if (t+1 < nt){
            float* a2=Asb[(t+1)&1]; float* b2=Bsb[(t+1)&1];
            sts4t(a2,k0,r0,ra0); sts4t(a2,k1,r1,ra1);
            sts4t(b2,k0,r0,rb0); sts4t(b2,k1,r1,rb1);
            __syncthreads();
        }
    }

    const float sc = 0.04419417382415922f;
    float* S = g_scores + (size_t)b*SLV*SLV;
    #pragma unroll
    for (int i=0;i<8;i++){
        size_t moff = (size_t)(bm+m0+i)*SLV + bn + n0;
        F2U u0,u1,u2,u3;
        u0.u=acc[i][0]; u1.u=acc[i][1]; u2.u=acc[i][2]; u3.u=acc[i][3];
        float vv[8] = {u0.f.x,u0.f.y,u1.f.x,u1.f.y,u2.f.x,u2.f.y,u3.f.x,u3.f.y};
        #pragma unroll
        for (int j=0;j<8;j++) S[moff+j] = vv[j]*sc + mask[moff+j];
    }
}

__global__ void __launch_bounds__(256)
pv_tc()
{
    extern __shared__ char sm_raw[];
    float* Asb[2]; float* Bsb[2];
    Asb[0]=(float*)sm_raw; Asb[1]=Asb[0]+16*SA; Bsb[0]=Asb[1]+16*SA; Bsb[1]=Bsb[0]+16*SA;
    int* kl   = (int*)(sm_raw + 4*16*SA*sizeof(float));
    int* nkbp = kl + 32;

    const int b = blockIdx.z, qb = blockIdx.y;
    const int bm = qb*128, bn = blockIdx.x*128;
    const int tid = threadIdx.x;
    if (tid==0){
        int c=0;
        for (int kb=0;kb<32;kb++) if (!g_flags[qb*32+kb]) kl[c++]=kb;
        *nkbp = c;
    }
    __syncthreads();
    const int nt = (*nkbp)*8;
    const float* A = g_scores + (size_t)b*SLV*SLV;
    // fallback reads V from xvT transposed: B[n][k] = xvT[b][bn+n][k]... note xvT is [b][d][s]
    const float* BT = g_xvT + (size_t)b*DIMV*SLV;

    const int c0=tid, c1=tid+256;
    const int ar0=c0>>2, ak0=(c0&3)*4;
    const int ar1=c1>>2, ak1=(c1&3)*4;
    // B loads: each thread loads 4 consecutive k for one n (row of xvT)
    const int bn0=c0>>2, bkk0=(c0&3)*4;
    const int bn1=c1>>2, bkk1=(c1&3)*4;

    const int tx=tid&15, ty=tid>>4;
    const int m0=ty*8, n0=tx*8;

    unsigned long long acc[8][4];
    #pragma unroll
    for (int i=0;i<8;i++){ acc[i][0]=acc[i][1]=acc[i][2]=acc[i][3]=0ull; }

    auto kof = [&](int t){ return kl[t>>3]*128 + (t&7)*16; };

    int kt = kof(0);
    float4 ra0 = *(const float4*)(A + (size_t)(bm+ar0)*SLV + kt+ak0);
    float4 ra1 = *(const float4*)(A + (size_t)(bm+ar1)*SLV + kt+ak1);
    float4 rb0 = *(const float4*)(BT + (size_t)(bn+bn0)*SLV + kt+bkk0);
    float4 rb1 = *(const float4*)(BT + (size_t)(bn+bn1)*SLV + kt+bkk1);
    sts4t(Asb[0],ak0,ar0,ra0); sts4t(Asb[0],ak1,ar1,ra1);
    sts4t(Bsb[0],bkk0,bn0,rb0); sts4t(Bsb[0],bkk1,bn1,rb1);
    __syncthreads();

    for (int t=0; t<nt; t++){
        if (t+1 < nt){
            int k2 = kof(t+1);
            ra0 = *(const float4*)(A + (size_t)(bm+ar0)*SLV + k2+ak0);
            ra1 = *(const float4*)(A + (size_t)(bm+ar1)*SLV + k2+ak1);
            rb0 = *(const float4*)(BT + (size_t)(bn+bn0)*SLV + k2+bkk0);
            rb1 = *(const float4*)(BT + (size_t)(bn+bn1)*SLV + k2+bkk1);
        }
        mm16(Asb[t&1], Bsb[t&1], m0, n0, acc);
        if (t+1 < nt){
            int bb=(t+1)&1;
            sts4t(Asb[bb],ak0,ar0,ra0); sts4t(Asb[bb],ak1,ar1,ra1);
            sts4t(Bsb[bb],bkk0,bn0,rb0); sts4t(Bsb[bb],bkk1,bn1,rb1);
            __syncthreads();
        }
    }

    #pragma unroll
    for (int i=0;i<8;i++){
        size_t off = (size_t)(b*SLV + bm+m0+i)*DIMV + bn + n0;
        F2U u0,u1,u2,u3;
        u0.u=acc[i][0]; u1.u=acc[i][1]; u2.u=acc[i][2]; u3.u=acc[i][3];
        float vv[8] = {u0.f.x,u0.f.y,u1.f.x,u1.f.y,u2.f.x,u2.f.y,u3.f.x,u3.f.y};
        #pragma unroll
        for (int j=0;j<8;j++) g_h[off+j] = vv[j];
    }
}
#endif  // TC_OK

// ---------------- launch ----------------
extern "C" void kernel_launch(void* const* d_in, const int* in_sizes, int n_in,
                              void* d_out, int out_size) {
    (void)in_sizes; (void)n_in; (void)out_size;
    const float* x    = (const float*)d_in[0];
    const float* mask = (const float*)d_in[1];
    float* out = (float*)d_out;

    float *Wk,*Wv,*Wo,*W1,*W2,*xk,*xvT,*h,*hres,*ff1;
    cudaGetSymbolAddress((void**)&Wk,   g_Wk);
    cudaGetSymbolAddress((void**)&Wv,   g_Wv);
    cudaGetSymbolAddress((void**)&Wo,   g_Wo);
    cudaGetSymbolAddress((void**)&W1,   g_W1);
    cudaGetSymbolAddress((void**)&W2,   g_W2);
    cudaGetSymbolAddress((void**)&xk,   g_xk);
    cudaGetSymbolAddress((void**)&xvT,  g_xvT);
    cudaGetSymbolAddress((void**)&h,    g_h);
    cudaGetSymbolAddress((void**)&hres, g_hres);
    cudaGetSymbolAddress((void**)&ff1,  g_ff1);

    cudaFuncSetAttribute(gemm_tc<0>, cudaFuncAttributeMaxDynamicSharedMemorySize, SMEM_REQ);
    cudaFuncSetAttribute(gemm_tc<1>, cudaFuncAttributeMaxDynamicSharedMemorySize, SMEM_REQ);
    cudaFuncSetAttribute(gemm_tc<2>, cudaFuncAttributeMaxDynamicSharedMemorySize, SMEM_REQ);
    cudaFuncSetAttribute(gemm_tc<3>, cudaFuncAttributeMaxDynamicSharedMemorySize, SMEM_REQ);
    cudaFuncSetAttribute(scores_tc,  cudaFuncAttributeMaxDynamicSharedMemorySize, SMEM_REQ);
    cudaFuncSetAttribute(pv_tc,      cudaFuncAttributeMaxDynamicSharedMemorySize, SMEM_REQ);

    dim3 blk(256);

    make_w_kernel<<<(DIMV*DIMV+255)/256, blk>>>((const float*)d_in[2],(const float*)d_in[3],(const float*)d_in[4], Wk, DIMV*DIMV);
    make_w_kernel<<<(DIMV*DIMV+255)/256, blk>>>((const float*)d_in[5],(const float*)d_in[6],(const float*)d_in[7], Wv, DIMV*DIMV);
    make_w_kernel<<<(DIMV*DIMV+255)/256, blk>>>((const float*)d_in[8],(const float*)d_in[9],(const float*)d_in[10], Wo, DIMV*DIMV);
    make_w_kernel<<<(HIDV*DIMV+255)/256, blk>>>((const float*)d_in[11],(const float*)d_in[12],(const float*)d_in[13], W1, HIDV*DIMV);
    make_w_kernel<<<(DIMV*HIDV+255)/256, blk>>>((const float*)d_in[14],(const float*)d_in[15],(const float*)d_in[16], W2, DIMV*HIDV);

    flags_kernel<<<dim3(32,32), blk>>>(mask);

    // xk = x @ Wk^T ; xvT[b][d][s] = (x @ Wv^T)^T
    gemm_tc<0><<<dim3(DIMV/128, TOK/128), blk, SMEM_REQ>>>(x, Wk, xk, nullptr, DIMV, DIMV);
    gemm_tc<3><<<dim3(DIMV/128, TOK/128), blk, SMEM_REQ>>>(x, Wv, xvT, nullptr, DIMV, DIMV);

    // attention
    scores_tc<<<dim3(32,32,NBATCH), blk, SMEM_REQ>>>(x, mask);
    softmax_kernel<<<TOK, blk>>>();
    pv_tc<<<dim3(DIMV/128, SLV/128, NBATCH), blk, SMEM_REQ>>>();

    // h_res = x + h @ Wo^T
    gemm_tc<1><<<dim3(DIMV/128, TOK/128), blk, SMEM_REQ>>>(h, Wo, hres, x, DIMV, DIMV);
    // ff1 = relu(h_res @ W1^T)
    gemm_tc<2><<<dim3(HIDV/128, TOK/128), blk, SMEM_REQ>>>(hres, W1, ff1, nullptr, DIMV, HIDV);
    // out = h_res + ff1 @ W2^T
    gemm_tc<1><<<dim3(DIMV/128, TOK/128), blk, SMEM_REQ>>>(ff1, W2, out, hres, HIDV, DIMV);
}

// round 15
// speedup vs baseline: 2.4976x; 1.0215x over previous
#include <cuda_runtime.h>
#include <cuda_bf16.h>
#include <math.h>

#define DIMV 512
#define HIDV 2048
#define NBATCH 4
#define SLV 4096
#define TOK (NBATCH*SLV)          // 16384
#define SCN (NBATCH*SLV*SLV)      // 67108864

#if defined(__CUDA_ARCH_FEAT_SM103_ALL) || defined(__CUDA_ARCH_FEAT_SM100_ALL) || defined(__CUDA_ARCH_FEAT_SM110_ALL)
#define TC_OK 1
#else
#define TC_OK 0
#endif

typedef __nv_bfloat16 bf16;

// ---------------- scratch (device globals: no allocation allowed) ----------------
__device__ bf16 g_Wk_h[DIMV*DIMV],  g_Wk_l[DIMV*DIMV];
__device__ bf16 g_Wv_h[DIMV*DIMV],  g_Wv_l[DIMV*DIMV];
__device__ bf16 g_Wo_h[DIMV*DIMV],  g_Wo_l[DIMV*DIMV];
__device__ bf16 g_W1_h[HIDV*DIMV],  g_W1_l[HIDV*DIMV];
__device__ bf16 g_W2_h[DIMV*HIDV],  g_W2_l[DIMV*HIDV];
__device__ bf16 g_xh[TOK*DIMV],     g_xl[TOK*DIMV];
__device__ bf16 g_xk_h[TOK*DIMV],   g_xk_l[TOK*DIMV];
__device__ bf16 g_xvT_h[NBATCH*DIMV*SLV], g_xvT_l[NBATCH*DIMV*SLV];
__device__ bf16 g_attn_h[SCN],      g_attn_l[SCN];          // 134MB each
__device__ bf16 g_h_h[TOK*DIMV],    g_h_l[TOK*DIMV];
__device__ float g_hres[TOK*DIMV];
__device__ bf16 g_hres_h[TOK*DIMV], g_hres_l[TOK*DIMV];
__device__ bf16 g_ff1_h[TOK*HIDV],  g_ff1_l[TOK*HIDV];
__device__ float g_scores[SCN];                              // 268MB
__device__ unsigned char g_flags[32*32];

// ---------------- smem layout (dynamic) ----------------
// 3 stages x 64KB: [Ah 16K][Al 16K][Bh 16K][Bl 16K]
#define TILEB   16384
#define STAGEB  65536
#define TMEMP_OFF 196608
#define MB_OFF    196616
#define KL_OFF    196648
#define NKB_OFF   196776
#define SMEM_REQ  197808

__device__ __forceinline__ unsigned smem_u32(const void* p){
    unsigned a;
    asm("{ .reg .u64 t; cvta.to.shared.u64 t, %1; cvt.u32.u64 %0, t; }" : "=r"(a) : "l"(p));
    return a;
}

// ---------------- fp32 -> (hi,lo) bf16 pair conversion ----------------
__device__ __forceinline__ void cvt_pair(float x0, float x1, unsigned &h, unsigned &l){
    union { __nv_bfloat162 b; unsigned u; } cv;
    cv.b = __floats2bfloat162_rn(x0, x1);      // .x (low 16) = x0, .y (high) = x1
    unsigned hu = cv.u;
    float f0 = __uint_as_float(hu << 16);
    float f1 = __uint_as_float(hu & 0xFFFF0000u);
    cv.b = __floats2bfloat162_rn(x0 - f0, x1 - f1);
    h = hu; l = cv.u;
}

// ================= small kernels =================
__global__ void make_w_bf(const float* __restrict__ mu, const float* __restrict__ ls,
                          const float* __restrict__ eps, bf16* __restrict__ H, bf16* __restrict__ L, int n2){
    int i = blockIdx.x*256 + threadIdx.x;
    if (i < n2){
        int e = i*2;
        float w0 = fmaf(expf(ls[e]),   eps[e],   mu[e]);
        float w1 = fmaf(expf(ls[e+1]), eps[e+1], mu[e+1]);
        unsigned h,l; cvt_pair(w0,w1,h,l);
        *(unsigned*)(H+e) = h; *(unsigned*)(L+e) = l;
    }
}

__global__ void split_bf(const float* __restrict__ X, bf16* __restrict__ H, bf16* __restrict__ L, int n2){
    int i = blockIdx.x*256 + threadIdx.x;
    if (i < n2){
        int e = i*2;
        unsigned h,l; cvt_pair(X[e], X[e+1], h, l);
        *(unsigned*)(H+e) = h; *(unsigned*)(L+e) = l;
    }
}

__global__ void flags_kernel(const float* __restrict__ mask){
    int qb=blockIdx.y, kb=blockIdx.x, tid=threadIdx.x;
    int any = 0;
    #pragma unroll 4
    for (int i=0;i<64;i++){
        int idx=i*256+tid; int r=idx>>7, c=idx&127;
        float v = mask[(size_t)(qb*128+r)*SLV + kb*128+c];
        any |= (v > -1e8f) ? 1 : 0;
    }
    int a = __syncthreads_or(any);
    if (tid==0) g_flags[qb*32+kb] = (a==0) ? 1 : 0;
}

// softmax: reads fp32 scores, writes attn hi/lo bf16; 16 consecutive cols/thread
__global__ void __launch_bounds__(256)
softmax_kernel()
{
    const int row = blockIdx.x;            // b*SLV + q
    const int q = row & (SLV-1);
    const int qb = q >> 7;
    const int tid = threadIdx.x;
    __shared__ unsigned char fl[32];
    __shared__ float red[8];
    if (tid < 32) fl[tid] = g_flags[qb*32 + tid];
    __syncthreads();
    const float* S = g_scores + (size_t)row*SLV;
    const int c0 = tid*16;
    const bool f = fl[tid>>3];

    float v[16];
    float mx = -3.402823466e38f;
    if (!f){
        #pragma unroll
        for (int j=0;j<4;j++){
            float4 t4 = *(const float4*)(S + c0 + j*4);
            v[j*4+0]=t4.x; v[j*4+1]=t4.y; v[j*4+2]=t4.z; v[j*4+3]=t4.w;
            mx = fmaxf(mx, fmaxf(fmaxf(t4.x,t4.y), fmaxf(t4.z,t4.w)));
        }
    }
    #pragma unroll
    for (int o=16;o>0;o>>=1) mx = fmaxf(mx, __shfl_xor_sync(0xffffffffu, mx, o));
    if ((tid&31)==0) red[tid>>5] = mx;
    __syncthreads();
    float m = red[0];
    #pragma unroll
    for (int w=1;w<8;w++) m = fmaxf(m, red[w]);
    __syncthreads();

    float s = 0.f;
    if (!f){
        #pragma unroll
        for (int i=0;i<16;i++){ float e = expf(v[i]-m); v[i]=e; s+=e; }
    }
    #pragma unroll
    for (int o=16;o>0;o>>=1) s += __shfl_xor_sync(0xffffffffu, s, o);
    if ((tid&31)==0) red[tid>>5] = s;
    __syncthreads();
    float tot = 0.f;
    #pragma unroll
    for (int w=0;w<8;w++) tot += red[w];
    float inv = 1.0f/tot;

    if (!f){
        unsigned hw[8], lw[8];
        #pragma unroll
        for (int j=0;j<8;j++) cvt_pair(v[2*j]*inv, v[2*j+1]*inv, hw[j], lw[j]);
        size_t off = (size_t)row*SLV + c0;
        *(uint4*)(g_attn_h + off)     = make_uint4(hw[0],hw[1],hw[2],hw[3]);
        *(uint4*)(g_attn_h + off + 8) = make_uint4(hw[4],hw[5],hw[6],hw[7]);
        *(uint4*)(g_attn_l + off)     = make_uint4(lw[0],lw[1],lw[2],lw[3]);
        *(uint4*)(g_attn_l + off + 8) = make_uint4(lw[4],lw[5],lw[6],lw[7]);
    }
}

#if TC_OK
// ---------------- tcgen05 helpers (only referenced from TC bodies) ----------------
__device__ __forceinline__ unsigned elect1(){
    unsigned p;
    asm volatile("{ .reg .pred p; elect.sync _|p, 0xFFFFFFFF; selp.b32 %0, 1, 0, p; }" : "=r"(p));
    return p;
}
#define MBAR_INIT(a,c) asm volatile("mbarrier.init.shared.b64 [%0], %1;" :: "r"(a), "r"(c) : "memory")
#define MBAR_WAIT(addr, ph) do { \
    unsigned _d; \
    asm volatile("{ .reg .pred P; mbarrier.try_wait.parity.acquire.cta.shared::cta.b64 P, [%1], %2; selp.b32 %0,1,0,P; }" \
        : "=r"(_d) : "r"(addr), "r"(ph) : "memory"); \
    while(!_d){ \
        asm volatile("{ .reg .pred P; mbarrier.try_wait.parity.acquire.cta.shared::cta.b64 P, [%1], %2, 0x989680; selp.b32 %0,1,0,P; }" \
            : "=r"(_d) : "r"(addr), "r"(ph) : "memory"); \
    } \
} while(0)
#define TC_ALLOC(a,n)  asm volatile("tcgen05.alloc.cta_group::1.sync.aligned.shared::cta.b32 [%0], %1;" :: "r"(a), "r"(n) : "memory")
#define TC_RELINQ()    asm volatile("tcgen05.relinquish_alloc_permit.cta_group::1.sync.aligned;")
#define TC_DEALLOC(t,n) asm volatile("tcgen05.dealloc.cta_group::1.sync.aligned.b32 %0, %1;" :: "r"(t), "r"(n))
#define TC_COMMIT(a)   asm volatile("tcgen05.commit.cta_group::1.mbarrier::arrive::one.shared::cluster.b64 [%0];" :: "r"(a) : "memory")
#define TC_FENCE_AFTER() asm volatile("tcgen05.fence::after_thread_sync;" ::: "memory")
#define TC_WAIT_LD()   asm volatile("tcgen05.wait::ld.sync.aligned;" ::: "memory")
#define FENCE_ASYNC()  asm volatile("fence.proxy.async.shared::cta;" ::: "memory")
#define SW128(o) ((o) ^ (((o)>>3)&0x70))

#define LDX32(r, ta) \
    asm volatile("tcgen05.ld.sync.aligned.32x32b.x32.b32 " \
        "{%0, %1, %2, %3, %4, %5, %6, %7, %8, %9, %10, %11, %12, %13, %14, %15, " \
        " %16, %17, %18, %19, %20, %21, %22, %23, %24, %25, %26, %27, %28, %29, %30, %31}, [%32];" \
        : "=r"((r)[0]),  "=r"((r)[1]),  "=r"((r)[2]),  "=r"((r)[3]), \
          "=r"((r)[4]),  "=r"((r)[5]),  "=r"((r)[6]),  "=r"((r)[7]), \
          "=r"((r)[8]),  "=r"((r)[9]),  "=r"((r)[10]), "=r"((r)[11]), \
          "=r"((r)[12]), "=r"((r)[13]), "=r"((r)[14]), "=r"((r)[15]), \
          "=r"((r)[16]), "=r"((r)[17]), "=r"((r)[18]), "=r"((r)[19]), \
          "=r"((r)[20]), "=r"((r)[21]), "=r"((r)[22]), "=r"((r)[23]), \
          "=r"((r)[24]), "=r"((r)[25]), "=r"((r)[26]), "=r"((r)[27]), \
          "=r"((r)[28]), "=r"((r)[29]), "=r"((r)[30]), "=r"((r)[31]) \
        : "r"(ta))

__device__ __forceinline__ unsigned long long mk_desc(unsigned addr){
    const unsigned long long base = (2ULL<<61) | (1ULL<<46) | (64ULL<<32) | (1ULL<<16);
    return base | (unsigned long long)((addr>>4)&0x3FFF);
}

#define IDESC 0x8200490u   // kind::f16: F32 accum, BF16xBF16, M=128, N=128

__device__ __forceinline__ void mma_ss(unsigned d, unsigned long long ad, unsigned long long bd, bool en){
    unsigned e = en ? 1u : 0u;
    asm volatile("{\n\t.reg .pred p;\n\tsetp.ne.u32 p, %4, 0;\n\t"
        "tcgen05.mma.cta_group::1.kind::f16 [%0], %1, %2, %3, {%5,%5,%5,%5}, p;\n\t}"
        :: "r"(d), "l"(ad), "l"(bd), "r"(IDESC), "r"(e), "r"(0u) : "memory");
}

__device__ __forceinline__ void issue_stage(unsigned tmem, unsigned sb, bool first){
    unsigned long long ah = mk_desc(sb);
    unsigned long long al = mk_desc(sb + TILEB);
    unsigned long long bh = mk_desc(sb + 2*TILEB);
    unsigned long long bl = mk_desc(sb + 3*TILEB);
    #pragma unroll
    for (int k=0;k<4;k++) mma_ss(tmem, ah+k*2, bh+k*2, !(first && k==0));
    #pragma unroll
    for (int k=0;k<4;k++) mma_ss(tmem, ah+k*2, bl+k*2, true);
    #pragma unroll
    for (int k=0;k<4;k++) mma_ss(tmem, al+k*2, bh+k*2, true);
}

// pure-copy tile loader: 128 rows x 64 bf16 (128B/row) -> SW128 smem
__device__ __forceinline__ void load_tile_bf(const bf16* __restrict__ P, size_t ld, int koff,
                                             char* dst, int tid){
    #pragma unroll
    for (int j=0;j<4;j++){
        int id = tid + 256*j;
        int row = id>>3, c = (id&7)*8;
        float4 v = *(const float4*)(P + (size_t)row*ld + koff + c);
        *(float4*)(dst + SW128((unsigned)(row*128 + c*2))) = v;
    }
}

__device__ __forceinline__ void load_stage(const bf16* Ah, const bf16* Al, size_t lda,
                                           const bf16* Bh, const bf16* Bl, size_t ldb,
                                           int koff, char* buf, int tid){
    load_tile_bf(Ah, lda, koff, buf,           tid);
    load_tile_bf(Al, lda, koff, buf +   TILEB, tid);
    load_tile_bf(Bh, ldb, koff, buf + 2*TILEB, tid);
    load_tile_bf(Bl, ldb, koff, buf + 3*TILEB, tid);
}

__device__ __forceinline__ int koff_of(const int* kl, int t){
    return kl ? (kl[t>>1]*128 + (t&1)*64) : (t<<6);
}

__device__ __forceinline__ void gemm_core(const bf16* Ah, const bf16* Al, size_t lda,
                                          const bf16* Bh, const bf16* Bl, size_t ldb,
                                          int nt, const int* kl,
                                          char* sm, unsigned smb, unsigned tmem){
    const int tid = threadIdx.x;
    const int wid = tid>>5;
    int ph[3] = {0,0,0};

    load_stage(Ah,Al,lda,Bh,Bl,ldb, koff_of(kl,0), sm, tid);
    if (nt>1) load_stage(Ah,Al,lda,Bh,Bl,ldb, koff_of(kl,1), sm + STAGEB, tid);
    FENCE_ASYNC();
    __syncthreads();

    for (int t=0; t<nt; t++){
        int b = t%3;
        if (wid==0 && elect1()){
            issue_stage(tmem, smb + b*STAGEB, t==0);
            TC_COMMIT(smb + MB_OFF + b*8);
        }
        int s = t+2;
        if (s < nt){
            int nb = s%3;
            if (s >= 3){ MBAR_WAIT(smb + MB_OFF + nb*8, ph[nb]); ph[nb]^=1; }
            load_stage(Ah,Al,lda,Bh,Bl,ldb, koff_of(kl,s), sm + nb*STAGEB, tid);
            FENCE_ASYNC();
            __syncthreads();
        } else if (t == nt-1){
            MBAR_WAIT(smb + MB_OFF + b*8, ph[b]); ph[b]^=1;
            TC_FENCE_AFTER();
        }
    }
    __syncthreads();
}

__device__ __forceinline__ unsigned gemm_prologue(unsigned smb){
    const int tid = threadIdx.x;
    if (tid==0){
        MBAR_INIT(smb+MB_OFF,   1);
        MBAR_INIT(smb+MB_OFF+8, 1);
        MBAR_INIT(smb+MB_OFF+16,1);
    }
    if ((tid>>5)==0){ TC_ALLOC(smb+TMEMP_OFF, 128); TC_RELINQ(); }
    __syncthreads();
    unsigned tmem;
    asm volatile("ld.shared.b32 %0, [%1];" : "=r"(tmem) : "r"(smb+TMEMP_OFF));
    return tmem;
}

// split-store 32 consecutive fp32 (from rr) as hi/lo bf16 at element offset off
__device__ __forceinline__ void split_store32(bf16* H, bf16* L, size_t off, const unsigned* rr){
    #pragma unroll
    for (int q=0;q<2;q++){
        unsigned hw[8], lw[8];
        #pragma unroll
        for (int j=0;j<8;j++)
            cvt_pair(__uint_as_float(rr[q*16+2*j]), __uint_as_float(rr[q*16+2*j+1]), hw[j], lw[j]);
        *(uint4*)(H+off+q*16)   = make_uint4(hw[0],hw[1],hw[2],hw[3]);
        *(uint4*)(H+off+q*16+8) = make_uint4(hw[4],hw[5],hw[6],hw[7]);
        *(uint4*)(L+off+q*16)   = make_uint4(lw[0],lw[1],lw[2],lw[3]);
        *(uint4*)(L+off+q*16+8) = make_uint4(lw[4],lw[5],lw[6],lw[7]);
    }
}
#else
// fallback helpers
__device__ __forceinline__ float rec2f(const bf16* H, const bf16* L, size_t i){
    return __bfloat162float(H[i]) + __bfloat162float(L[i]);
}
__device__ __forceinline__ void split1f(float x, bf16* H, bf16* L, size_t i){
    bf16 hb = __float2bfloat16_rn(x);
    H[i] = hb;
    L[i] = __float2bfloat16_rn(x - __bfloat162float(hb));
}
#endif  // TC_OK

// ---------------- generic NT GEMM: C[M,N] = A * B^T ----------------
// EPI: 0 = bf16 hi/lo out; 3 = transposed bf16 hi/lo (xvT); 4 = fp32(+aux)+bf16 hi/lo (hres);
//      5 = relu + bf16 hi/lo; 6 = fp32 + aux
template<int EPI>
__global__ void __launch_bounds__(256)
gemm_tc(const bf16* __restrict__ Ah, const bf16* __restrict__ Al,
        const bf16* __restrict__ Bh, const bf16* __restrict__ Bl,
        int K, int N, bf16* __restrict__ OH, bf16* __restrict__ OL,
        float* __restrict__ OF, const float* __restrict__ aux)
{
#if TC_OK
    extern __shared__ char sm_raw[];
    unsigned smb0 = smem_u32(sm_raw);
    unsigned smb = (smb0 + 1023) & ~1023u;
    char* sm = sm_raw + (smb - smb0);

    const int tid = threadIdx.x, wid = tid>>5, lane = tid&31;
    const int bm = blockIdx.y*128, bn = blockIdx.x*128;

    unsigned tmem = gemm_prologue(smb);
    gemm_core(Ah + (size_t)bm*K, Al + (size_t)bm*K, K,
              Bh + (size_t)bn*K, Bl + (size_t)bn*K, K,
              K>>6, nullptr, sm, smb, tmem);

    const int band = wid&3;
    if (EPI != 3){
        const int m = bm + band*32 + lane;
        #pragma unroll
        for (int cc=0; cc<2; cc++){
            int c0 = (wid>>2)*64 + cc*32;
            unsigned rr[32];
            LDX32(rr, tmem + c0);
            TC_WAIT_LD();
            size_t off = (size_t)m*N + bn + c0;
            if (EPI==0){
                split_store32(OH, OL, off, rr);
            } else if (EPI==4){
                #pragma unroll
                for (int j=0;j<32;j+=4){
                    float4 x = *(const float4*)(aux+off+j);
                    x.x += __uint_as_float(rr[j]);   x.y += __uint_as_float(rr[j+1]);
                    x.z += __uint_as_float(rr[j+2]); x.w += __uint_as_float(rr[j+3]);
                    *(float4*)(OF+off+j) = x;
                    rr[j]=__float_as_uint(x.x); rr[j+1]=__float_as_uint(x.y);
                    rr[j+2]=__float_as_uint(x.z); rr[j+3]=__float_as_uint(x.w);
                }
                split_store32(OH, OL, off, rr);
            } else if (EPI==5){
                #pragma unroll
                for (int j=0;j<32;j++)
                    rr[j] = __float_as_uint(fmaxf(__uint_as_float(rr[j]), 0.f));
                split_store32(OH, OL, off, rr);
            } else { // EPI==6
                #pragma unroll
                for (int j=0;j<32;j+=4){
                    float4 x = *(const float4*)(aux+off+j);
                    x.x += __uint_as_float(rr[j]);   x.y += __uint_as_float(rr[j+1]);
                    x.z += __uint_as_float(rr[j+2]); x.w += __uint_as_float(rr[j+3]);
                    *(float4*)(OF+off+j) = x;
                }
            }
        }
    } else {
        // transposed hi/lo store: xvT[b][d][s]
        const int b = bm >> 12;
        const int s0 = (bm & 4095) + band*32;
        float* tb = (float*)(sm + wid*4608);   // 32 x 36 floats per warp
        #pragma unroll
        for (int cc=0; cc<2; cc++){
            int c0 = (wid>>2)*64 + cc*32;
            unsigned rr[32];
            LDX32(rr, tmem + c0);
            TC_WAIT_LD();
            #pragma unroll
            for (int j=0;j<32;j++) tb[j*36 + lane] = __uint_as_float(rr[j]);
            __syncwarp();
            unsigned tr[32];
            #pragma unroll
            for (int i=0;i<32;i++) tr[i] = __float_as_uint(tb[lane*36+i]);
            size_t off = (size_t)b*DIMV*SLV + (size_t)(bn + c0 + lane)*SLV + s0;
            split_store32(OH, OL, off, tr);
            __syncwarp();
        }
    }
    __syncthreads();
    if (wid==0) TC_DEALLOC(tmem, 128);
#else
    // fallback body (never runs on sm_103a; keeps feature-less pass valid)
    int bm = blockIdx.y*128, bn = blockIdx.x*128;
    for (int e = threadIdx.x; e < 128*128; e += 256){
        int i = e>>7, j = e&127;
        size_t m = bm+i, n = bn+j;
        float acc=0;
        for (int k=0;k<K;k++)
            acc += rec2f(Ah,Al,m*K+k) * rec2f(Bh,Bl,n*K+k);
        if (EPI==0) split1f(acc, OH, OL, m*N+n);
        else if (EPI==3){
            int b = bm>>12; size_t s = (bm&4095)+i;
            split1f(acc, OH, OL, (size_t)b*DIMV*SLV + (size_t)(bn+j)*SLV + s);
        } else if (EPI==4){
            float r = acc + aux[m*N+n]; OF[m*N+n]=r; split1f(r, OH, OL, m*N+n);
        } else if (EPI==5) split1f(fmaxf(acc,0.f), OH, OL, m*N+n);
        else OF[m*N+n] = acc + aux[m*N+n];
    }
#endif
}

// ---------------- scores: S = (x @ xk^T)/sqrt(D) + mask ----------------
__global__ void __launch_bounds__(256)
scores_tc(const float* __restrict__ mask)
{
#if TC_OK
    const int b = blockIdx.z, qb = blockIdx.y, kb = blockIdx.x;
    if (g_flags[qb*32+kb]) return;

    extern __shared__ char sm_raw[];
    unsigned smb0 = smem_u32(sm_raw);
    unsigned smb = (smb0 + 1023) & ~1023u;
    char* sm = sm_raw + (smb - smb0);

    const int tid = threadIdx.x, wid = tid>>5, lane = tid&31;
    const int bm = qb*128, bn = kb*128;
    size_t aoff = (size_t)b*SLV*DIMV + (size_t)bm*DIMV;
    size_t boff = (size_t)b*SLV*DIMV + (size_t)bn*DIMV;

    unsigned tmem = gemm_prologue(smb);
    gemm_core(g_xh + aoff, g_xl + aoff, DIMV,
              g_xk_h + boff, g_xk_l + boff, DIMV,
              DIMV>>6, nullptr, sm, smb, tmem);

    const float sc = 0.04419417382415922f;
    float* S = g_scores + (size_t)b*SLV*SLV;
    const int m = bm + (wid&3)*32 + lane;
    #pragma unroll
    for (int cc=0; cc<2; cc++){
        int c0 = (wid>>2)*64 + cc*32;
        unsigned rr[32];
        LDX32(rr, tmem + c0);
        TC_WAIT_LD();
        size_t off = (size_t)m*SLV + bn + c0;
        #pragma unroll
        for (int j=0;j<32;j+=4){
            float4 mk = *(const float4*)(mask+off+j);
            float4 v;
            v.x = __uint_as_float(rr[j])  *sc + mk.x;
            v.y = __uint_as_float(rr[j+1])*sc + mk.y;
            v.z = __uint_as_float(rr[j+2])*sc + mk.z;
            v.w = __uint_as_float(rr[j+3])*sc + mk.w;
            *(float4*)(S+off+j) = v;
        }
    }
    __syncthreads();
    if (wid==0) TC_DEALLOC(tmem, 128);
#else
    const int b = blockIdx.z, qb=blockIdx.y, kb=blockIdx.x;
    if (g_flags[qb*32+kb]) return;
    int bm = qb*128, bn = kb*128;
    const float sc = 0.04419417382415922f;
    for (int e = threadIdx.x; e < 128*128; e += 256){
        int i=e>>7, j=e&127;
        size_t m = bm+i, n = bn+j;
        float acc=0;
        size_t ao = (size_t)b*SLV*DIMV + m*DIMV, bo = (size_t)b*SLV*DIMV + n*DIMV;
        for (int k=0;k<DIMV;k++)
            acc += rec2f(g_xh,g_xl,ao+k) * rec2f(g_xk_h,g_xk_l,bo+k);
        size_t off = (size_t)b*SLV*SLV + m*SLV + n;
        g_scores[off] = acc*sc + mask[m*SLV+n];
    }
#endif
}

// ---------------- PV: h = attn @ xv via xvT, skip masked k-tiles ----------------
__global__ void __launch_bounds__(256)
pv_tc()
{
#if TC_OK
    extern __shared__ char sm_raw[];
    unsigned smb0 = smem_u32(sm_raw);
    unsigned smb = (smb0 + 1023) & ~1023u;
    char* sm = sm_raw + (smb - smb0);

    const int b = blockIdx.z, qb = blockIdx.y;
    const int bm = qb*128, bn = blockIdx.x*128;
    const int tid = threadIdx.x, wid = tid>>5, lane = tid&31;

    int* kl = (int*)(sm + KL_OFF);
    int* nkb_p = (int*)(sm + NKB_OFF);
    if (tid==0){
        MBAR_INIT(smb+MB_OFF,   1);
        MBAR_INIT(smb+MB_OFF+8, 1);
        MBAR_INIT(smb+MB_OFF+16,1);
        int c=0;
        for (int kb=0;kb<32;kb++) if (!g_flags[qb*32+kb]) kl[c++]=kb;
        *nkb_p = c;
    }
    if (wid==0){ TC_ALLOC(smb+TMEMP_OFF, 128); TC_RELINQ(); }
    __syncthreads();
    unsigned tmem;
    asm volatile("ld.shared.b32 %0, [%1];" : "=r"(tmem) : "r"(smb+TMEMP_OFF));
    const int nt = (*nkb_p)*2;

    size_t aoff = (size_t)b*SLV*SLV + (size_t)bm*SLV;
    size_t boff = (size_t)b*DIMV*SLV + (size_t)bn*SLV;
    gemm_core(g_attn_h + aoff, g_attn_l + aoff, SLV,
              g_xvT_h + boff, g_xvT_l + boff, SLV,
              nt, kl, sm, smb, tmem);

    const int m = bm + (wid&3)*32 + lane;
    #pragma unroll
    for (int cc=0; cc<2; cc++){
        int c0 = (wid>>2)*64 + cc*32;
        unsigned rr[32];
        LDX32(rr, tmem + c0);
        TC_WAIT_LD();
        size_t off = (size_t)(b*SLV + m)*DIMV + bn + c0;
        split_store32(g_h_h, g_h_l, off, rr);
    }
    __syncthreads();
    if (wid==0) TC_DEALLOC(tmem, 128);
#else
    const int b = blockIdx.z, qb = blockIdx.y;
    int bm = qb*128, bn = blockIdx.x*128;
    for (int e = threadIdx.x; e < 128*128; e += 256){
        int i=e>>7, j=e&127;
        size_t m = bm+i, n = bn+j;
        float acc=0;
        for (int kb=0;kb<32;kb++){
            if (g_flags[qb*32+kb]) continue;
            size_t ao = (size_t)b*SLV*SLV + m*SLV;
            size_t bo = (size_t)b*DIMV*SLV + n*SLV;
            for (int k=kb*128;k<kb*128+128;k++)
                acc += rec2f(g_attn_h,g_attn_l,ao+k) * rec2f(g_xvT_h,g_xvT_l,bo+k);
        }
        split1f(acc, g_h_h, g_h_l, (size_t)(b*SLV+m)*DIMV + n);
    }
#endif
}

// ---------------- launch ----------------
extern "C" void kernel_launch(void* const* d_in, const int* in_sizes, int n_in,
                              void* d_out, int out_size) {
    (void)in_sizes; (void)n_in; (void)out_size;
    const float* x    = (const float*)d_in[0];
    const float* mask = (const float*)d_in[1];
    float* out = (float*)d_out;

    bf16 *Wk_h,*Wk_l,*Wv_h,*Wv_l,*Wo_h,*Wo_l,*W1_h,*W1_l,*W2_h,*W2_l;
    bf16 *xh,*xl,*xk_h,*xk_l,*xvT_h,*xvT_l,*h_h,*h_l,*hres_h,*hres_l,*ff1_h,*ff1_l;
    float *hres;
    cudaGetSymbolAddress((void**)&Wk_h, g_Wk_h); cudaGetSymbolAddress((void**)&Wk_l, g_Wk_l);
    cudaGetSymbolAddress((void**)&Wv_h, g_Wv_h); cudaGetSymbolAddress((void**)&Wv_l, g_Wv_l);
    cudaGetSymbolAddress((void**)&Wo_h, g_Wo_h); cudaGetSymbolAddress((void**)&Wo_l, g_Wo_l);
    cudaGetSymbolAddress((void**)&W1_h, g_W1_h); cudaGetSymbolAddress((void**)&W1_l, g_W1_l);
    cudaGetSymbolAddress((void**)&W2_h, g_W2_h); cudaGetSymbolAddress((void**)&W2_l, g_W2_l);
    cudaGetSymbolAddress((void**)&xh,   g_xh);   cudaGetSymbolAddress((void**)&xl,   g_xl);
    cudaGetSymbolAddress((void**)&xk_h, g_xk_h); cudaGetSymbolAddress((void**)&xk_l, g_xk_l);
    cudaGetSymbolAddress((void**)&xvT_h,g_xvT_h);cudaGetSymbolAddress((void**)&xvT_l,g_xvT_l);
    cudaGetSymbolAddress((void**)&h_h,  g_h_h);  cudaGetSymbolAddress((void**)&h_l,  g_h_l);
    cudaGetSymbolAddress((void**)&hres_h,g_hres_h); cudaGetSymbolAddress((void**)&hres_l,g_hres_l);
    cudaGetSymbolAddress((void**)&ff1_h,g_ff1_h); cudaGetSymbolAddress((void**)&ff1_l,g_ff1_l);
    cudaGetSymbolAddress((void**)&hres, g_hres);

    cudaFuncSetAttribute(gemm_tc<0>, cudaFuncAttributeMaxDynamicSharedMemorySize, SMEM_REQ);
    cudaFuncSetAttribute(gemm_tc<3>, cudaFuncAttributeMaxDynamicSharedMemorySize, SMEM_REQ);
    cudaFuncSetAttribute(gemm_tc<4>, cudaFuncAttributeMaxDynamicSharedMemorySize, SMEM_REQ);
    cudaFuncSetAttribute(gemm_tc<5>, cudaFuncAttributeMaxDynamicSharedMemorySize, SMEM_REQ);
    cudaFuncSetAttribute(gemm_tc<6>, cudaFuncAttributeMaxDynamicSharedMemorySize, SMEM_REQ);
    cudaFuncSetAttribute(scores_tc,  cudaFuncAttributeMaxDynamicSharedMemorySize, SMEM_REQ);
    cudaFuncSetAttribute(pv_tc,      cudaFuncAttributeMaxDynamicSharedMemorySize, SMEM_REQ);

    dim3 blk(256);

    make_w_bf<<<(DIMV*DIMV/2+255)/256, blk>>>((const float*)d_in[2],(const float*)d_in[3],(const float*)d_in[4], Wk_h, Wk_l, DIMV*DIMV/2);
    make_w_bf<<<(DIMV*DIMV/2+255)/256, blk>>>((const float*)d_in[5],(const float*)d_in[6],(const float*)d_in[7], Wv_h, Wv_l, DIMV*DIMV/2);
    make_w_bf<<<(DIMV*DIMV/2+255)/256, blk>>>((const float*)d_in[8],(const float*)d_in[9],(const float*)d_in[10], Wo_h, Wo_l, DIMV*DIMV/2);
    make_w_bf<<<(HIDV*DIMV/2+255)/256, blk>>>((const float*)d_in[11],(const float*)d_in[12],(const float*)d_in[13], W1_h, W1_l, HIDV*DIMV/2);
    make_w_bf<<<(DIMV*HIDV/2+255)/256, blk>>>((const float*)d_in[14],(const float*)d_in[15],(const float*)d_in[16], W2_h, W2_l, DIMV*HIDV/2);
    split_bf<<<(TOK*DIMV/2+255)/256, blk>>>(x, xh, xl, TOK*DIMV/2);

    flags_kernel<<<dim3(32,32), blk>>>(mask);

    // xk = x @ Wk^T (bf16 hi/lo out) ; xvT = (x @ Wv^T)^T (bf16 hi/lo)
    gemm_tc<0><<<dim3(DIMV/128, TOK/128), blk, SMEM_REQ>>>(xh, xl, Wk_h, Wk_l, DIMV, DIMV, xk_h, xk_l, nullptr, nullptr);
    gemm_tc<3><<<dim3(DIMV/128, TOK/128), blk, SMEM_REQ>>>(xh, xl, Wv_h, Wv_l, DIMV, DIMV, xvT_h, xvT_l, nullptr, nullptr);

    // attention
    scores_tc<<<dim3(32,32,NBATCH), blk, SMEM_REQ>>>(mask);
    softmax_kernel<<<TOK, blk>>>();
    pv_tc<<<dim3(DIMV/128, SLV/128, NBATCH), blk, SMEM_REQ>>>();

    // h_res = x + h @ Wo^T  (fp32 + bf16 hi/lo)
    gemm_tc<4><<<dim3(DIMV/128, TOK/128), blk, SMEM_REQ>>>(h_h, h_l, Wo_h, Wo_l, DIMV, DIMV, hres_h, hres_l, hres, x);
    // ff1 = relu(h_res @ W1^T)  (bf16 hi/lo)
    gemm_tc<5><<<dim3(HIDV/128, TOK/128), blk, SMEM_REQ>>>(hres_h, hres_l, W1_h, W1_l, DIMV, HIDV, ff1_h, ff1_l, nullptr, nullptr);
    // out = h_res + ff1 @ W2^T  (fp32)
    gemm_tc<6><<<dim3(DIMV/128, TOK/128), blk, SMEM_REQ>>>(ff1_h, ff1_l, W2_h, W2_l, HIDV, DIMV, nullptr, nullptr, out, hres);
}